// round 6
// baseline (speedup 1.0000x reference)
#include <cuda_runtime.h>
#include <cuda_bf16.h>
#include <math.h>
#include <stdint.h>

// ---------------------------------------------------------------------------
#define C_DIM   192
#define NH      6
#define NWIN    4096
#define M_TOT   262144
#define HIDDEN  768
#define QKV_NP  640          // padded qkv output cols
#define QKV_NR  576
#define SCALE_F 0.17677669529663687f

// ---------------------------------------------------------------------------
// One shared scratch pool; logical buffers assigned time-disjoint offsets.
//   bytes per bf16 plane:
//     CD  plane (M_TOT*192) = 100,663,296
//     QKV plane (M_TOT*640) = 335,544,320
//     HID plane (M_TOT*768) = 402,653,184
// Layout (byte offsets):
//   qh 0            ql 335,544,320          (live: qkv gemm -> attention)
//   hh 0            hl 402,653,184          (live: fc1 -> fc2)   [overlaps q]
//   xh 805,306,368  xl 905,969,664          (live: prep -> qkv gemm)
//   ah 805,306,368  al 905,969,664          (live: attention -> proj) [overlaps x]
//   th 1,006,632,960 tl 1,107,296,256       (live: proj->ln1, fc2->ln2)
//   x1h 1,207,959,552 x1l 1,308,622,848     (live: ln1 -> ln2)
// Pool = 1,409,286,144 bytes (1.31 GiB) — well under the 2 GB reloc limit.
// ---------------------------------------------------------------------------
#define SZ_CD  ((size_t)M_TOT * C_DIM * 2)
#define SZ_QK  ((size_t)M_TOT * QKV_NP * 2)
#define SZ_HI  ((size_t)M_TOT * HIDDEN * 2)
#define OFF_Q  ((size_t)0)
#define OFF_H  ((size_t)0)
#define OFF_X  (2 * SZ_QK + SZ_CD + (size_t)33554432)   // 805,306,368
#define OFF_T  (OFF_X + 2 * SZ_CD)                       // 1,006,632,960
#define OFF_X1 (OFF_T + 2 * SZ_CD)                       // 1,207,959,552
#define POOLSZ (OFF_X1 + 2 * SZ_CD)

__device__ __align__(256) char g_pool[POOLSZ];

__device__ __nv_bfloat16 g_wqh[QKV_NP * C_DIM];
__device__ __nv_bfloat16 g_wql[QKV_NP * C_DIM];
__device__ __nv_bfloat16 g_wph[C_DIM * C_DIM];
__device__ __nv_bfloat16 g_wpl[C_DIM * C_DIM];
__device__ __nv_bfloat16 g_w1h[HIDDEN * C_DIM];
__device__ __nv_bfloat16 g_w1l[HIDDEN * C_DIM];
__device__ __nv_bfloat16 g_w2h[C_DIM * HIDDEN];
__device__ __nv_bfloat16 g_w2l[C_DIM * HIDDEN];
__device__ float         g_qb [QKV_NP];

// ---------------------------------------------------------------------------
__device__ __forceinline__ int map_row(int m) {
    int w    = m >> 6;
    int t    = m & 63;
    int b    = w >> 10;
    int widx = w & 1023;
    int wh   = widx >> 5;
    int ww   = widx & 31;
    int r    = t >> 3;
    int c    = t & 7;
    int h    = (wh * 8 + r + 4) & 255;
    int wc   = (ww * 8 + c + 4) & 255;
    return (b << 16) | (h << 8) | wc;
}

__device__ __forceinline__ uint32_t smem_to_u32(const void* p) {
    uint32_t a;
    asm("{ .reg .u64 t; cvta.to.shared.u64 t, %1; cvt.u32.u64 %0, t; }" : "=r"(a) : "l"(p));
    return a;
}

#define CP_ASYNC16(dst, src) \
    asm volatile("cp.async.cg.shared.global [%0], [%1], 16;" :: "r"(dst), "l"(src))
#define CP_COMMIT() asm volatile("cp.async.commit_group;")
#define CP_WAIT(n)  asm volatile("cp.async.wait_group %0;" :: "n"(n))

#define LDM_X4(r0, r1, r2, r3, addr) \
    asm volatile("ldmatrix.sync.aligned.m8n8.x4.shared.b16 {%0,%1,%2,%3}, [%4];" \
                 : "=r"(r0), "=r"(r1), "=r"(r2), "=r"(r3) : "r"(addr))

#define MMA_BF16(d, a, b) \
    asm volatile("mma.sync.aligned.m16n8k16.row.col.f32.bf16.bf16.f32 " \
                 "{%0,%1,%2,%3}, {%4,%5,%6,%7}, {%8,%9}, {%0,%1,%2,%3};" \
                 : "+f"((d)[0]), "+f"((d)[1]), "+f"((d)[2]), "+f"((d)[3]) \
                 : "r"((a)[0]), "r"((a)[1]), "r"((a)[2]), "r"((a)[3]), \
                   "r"((b)[0]), "r"((b)[1]))

__device__ __forceinline__ uint32_t pk_bf2(float x, float y) {
    __nv_bfloat162 t = __floats2bfloat162_rn(x, y);
    return *(uint32_t*)&t;
}
__device__ __forceinline__ void split_pair2(float x, float y, uint32_t& hi, uint32_t& lo) {
    __nv_bfloat16 hx = __float2bfloat16_rn(x);
    __nv_bfloat16 hy = __float2bfloat16_rn(y);
    hi = (uint32_t)__bfloat16_as_ushort(hx) | ((uint32_t)__bfloat16_as_ushort(hy) << 16);
    lo = pk_bf2(x - __bfloat162float(hx), y - __bfloat162float(hy));
}
__device__ __forceinline__ float rec(const __nv_bfloat16 h, const __nv_bfloat16 l) {
    return __bfloat162float(h) + __bfloat162float(l);
}

// ---------------------------------------------------------------------------
// Prep kernels
// ---------------------------------------------------------------------------
__global__ __launch_bounds__(256) void prep_x(
    const float* __restrict__ x, __nv_bfloat16* __restrict__ xh, __nv_bfloat16* __restrict__ xl)
{
    int idx = blockIdx.x * 256 + threadIdx.x;      // M_TOT * 48
    int m = idx / 48, c4 = idx % 48;
    float4 v = *(const float4*)(x + (size_t)map_row(m) * C_DIM + c4 * 4);
    uint32_t h0, l0, h1, l1;
    split_pair2(v.x, v.y, h0, l0);
    split_pair2(v.z, v.w, h1, l1);
    size_t o = (size_t)m * C_DIM + c4 * 4;
    *(uint2*)(xh + o) = make_uint2(h0, h1);
    *(uint2*)(xl + o) = make_uint2(l0, l1);
}

__global__ __launch_bounds__(256) void prep_w(
    const float* __restrict__ w, __nv_bfloat16* __restrict__ wh, __nv_bfloat16* __restrict__ wl,
    int rows, int K)
{
    int idx = blockIdx.x * 256 + threadIdx.x;      // padRows * K/4
    int k4 = K / 4;
    int row = idx / k4, c4 = idx % k4;
    float4 v = make_float4(0.f, 0.f, 0.f, 0.f);
    if (row < rows) v = *(const float4*)(w + (size_t)row * K + c4 * 4);
    uint32_t h0, l0, h1, l1;
    split_pair2(v.x, v.y, h0, l0);
    split_pair2(v.z, v.w, h1, l1);
    size_t o = (size_t)row * K + c4 * 4;
    *(uint2*)(wh + o) = make_uint2(h0, h1);
    *(uint2*)(wl + o) = make_uint2(l0, l1);
}

__global__ void prep_b(const float* __restrict__ b, float* __restrict__ bp) {
    int i = blockIdx.x * 256 + threadIdx.x;
    if (i < QKV_NP) bp[i] = (i < QKV_NR) ? b[i] : 0.f;
}

// ---------------------------------------------------------------------------
// Split-bf16 HMMA GEMM with cp.async 3-stage pipeline.
// C[m,n] = sum_k A[m,k] W[n,k] + bias[n]; A,W pre-split hi/lo planes.
// BM=128, BK=32, BNT in {64,128}. 256 threads, warps 4(M) x 2(N).
// ---------------------------------------------------------------------------
#define BM   128
#define BK   32
#define NSTG 3

template<int BNT, bool SCATTER, bool DOGELU>
__global__ __launch_bounds__(256, (BNT == 64) ? 2 : 1) void mm_split(
    const __nv_bfloat16* __restrict__ Ah, const __nv_bfloat16* __restrict__ Al,
    const __nv_bfloat16* __restrict__ Wh, const __nv_bfloat16* __restrict__ Wl,
    const float* __restrict__ bias,
    __nv_bfloat16* __restrict__ Ohi, __nv_bfloat16* __restrict__ Olo,
    int N, int K)
{
    constexpr int ATB  = 128 * 80;                 // bytes per A plane tile
    constexpr int BTB  = BNT * 80;
    constexpr int SST_ = 2 * ATB + 2 * BTB;        // stage bytes
    constexpr int WN   = BNT / 2;
    constexpr int NT8  = WN / 8;
    constexpr int NT2  = WN / 16;
    constexpr int BCH  = (BNT == 128) ? 2 : 1;

    extern __shared__ char sm[];
    const uint32_t sbase = smem_to_u32(sm);

    const int tid = threadIdx.x, wid = tid >> 5, lane = tid & 31;
    const int warpM = wid & 3, warpN = wid >> 2;
    const int rowBase = blockIdx.y * BM;
    const int colBase = blockIdx.x * BNT;
    const int nch = K / BK;

    // staging descriptors (16B chunks; 4 chunks per 64B k-row-slice)
    const __nv_bfloat16* aSrcH[2]; const __nv_bfloat16* aSrcL[2];
    uint32_t aDst[2];
    #pragma unroll
    for (int t = 0; t < 2; t++) {
        int cidx = tid + t * 256;
        int row = cidx >> 2, kc = cidx & 3;
        size_t go = (size_t)(rowBase + row) * K + kc * 8;
        aSrcH[t] = Ah + go; aSrcL[t] = Al + go;
        aDst[t] = row * 80 + kc * 16;
    }
    const __nv_bfloat16* bSrcH[BCH]; const __nv_bfloat16* bSrcL[BCH];
    uint32_t bDst[BCH];
    #pragma unroll
    for (int t = 0; t < BCH; t++) {
        int cidx = tid + t * 256;
        int row = cidx >> 2, kc = cidx & 3;
        size_t go = (size_t)(colBase + row) * K + kc * 8;
        bSrcH[t] = Wh + go; bSrcL[t] = Wl + go;
        bDst[t] = row * 80 + kc * 16;
    }

    auto issue = [&](int s, int it) {
        uint32_t sb = sbase + s * SST_;
        int k0 = it * BK;
        #pragma unroll
        for (int t = 0; t < 2; t++) {
            CP_ASYNC16(sb + aDst[t],       aSrcH[t] + k0);
            CP_ASYNC16(sb + ATB + aDst[t], aSrcL[t] + k0);
        }
        #pragma unroll
        for (int t = 0; t < BCH; t++) {
            CP_ASYNC16(sb + 2 * ATB + bDst[t],       bSrcH[t] + k0);
            CP_ASYNC16(sb + 2 * ATB + BTB + bDst[t], bSrcL[t] + k0);
        }
        CP_COMMIT();
    };

    // ldmatrix coordinates
    const uint32_t aRowL = (uint32_t)(warpM * 32 + (lane & 15));
    const uint32_t aColB = (uint32_t)(((lane >> 4) * 8) * 2);
    const uint32_t bRowL = (uint32_t)(warpN * WN + (lane & 7) + ((lane >> 4) << 3));
    const uint32_t bColB = (uint32_t)((((lane >> 3) & 1) * 8) * 2);

    float acc[2][NT8][4] = {};

    issue(0, 0);
    issue(1, 1);

    for (int it = 0; it < nch; it++) {
        CP_WAIT(1);
        __syncthreads();
        const uint32_t stg = sbase + (it % NSTG) * SST_;

        #pragma unroll
        for (int kk = 0; kk < BK; kk += 16) {
            uint32_t ah[2][4], al[2][4], bh[NT2][4], bl[NT2][4];
            #pragma unroll
            for (int mt = 0; mt < 2; mt++) {
                uint32_t off = (aRowL + mt * 16) * 80 + aColB + kk * 2;
                LDM_X4(ah[mt][0], ah[mt][1], ah[mt][2], ah[mt][3], stg + off);
                LDM_X4(al[mt][0], al[mt][1], al[mt][2], al[mt][3], stg + ATB + off);
            }
            #pragma unroll
            for (int nt2 = 0; nt2 < NT2; nt2++) {
                uint32_t off = 2 * ATB + (bRowL + nt2 * 16) * 80 + bColB + kk * 2;
                LDM_X4(bh[nt2][0], bh[nt2][1], bh[nt2][2], bh[nt2][3], stg + off);
                LDM_X4(bl[nt2][0], bl[nt2][1], bl[nt2][2], bl[nt2][3], stg + BTB + off);
            }
            #pragma unroll
            for (int mt = 0; mt < 2; mt++) {
                #pragma unroll
                for (int n = 0; n < NT8; n++) {
                    uint32_t bfh[2] = { bh[n >> 1][(n & 1) * 2], bh[n >> 1][(n & 1) * 2 + 1] };
                    uint32_t bfl[2] = { bl[n >> 1][(n & 1) * 2], bl[n >> 1][(n & 1) * 2 + 1] };
                    MMA_BF16(acc[mt][n], ah[mt], bfh);
                    MMA_BF16(acc[mt][n], ah[mt], bfl);
                    MMA_BF16(acc[mt][n], al[mt], bfh);
                }
            }
        }

        int nxt = it + NSTG - 1;
        if (nxt < nch) issue(nxt % NSTG, nxt);
        else           CP_COMMIT();
    }

    // ---- epilogue: split + store hi/lo ----
    const int qid = lane >> 2;
    const int cid2 = (lane & 3) * 2;
    #pragma unroll
    for (int mt = 0; mt < 2; mt++) {
        #pragma unroll
        for (int hf = 0; hf < 2; hf++) {
            int row = rowBase + warpM * 32 + mt * 16 + qid + hf * 8;
            if (SCATTER) row = map_row(row);
            size_t rb = (size_t)row * N;
            #pragma unroll
            for (int n = 0; n < NT8; n++) {
                int col = colBase + warpN * WN + n * 8 + cid2;
                float2 bv = *(const float2*)(bias + col);
                float ox = acc[mt][n][hf * 2 + 0] + bv.x;
                float oy = acc[mt][n][hf * 2 + 1] + bv.y;
                if (DOGELU) {
                    ox = 0.5f * ox * (1.0f + erff(ox * 0.70710678118654752f));
                    oy = 0.5f * oy * (1.0f + erff(oy * 0.70710678118654752f));
                }
                uint32_t hi, lo;
                split_pair2(ox, oy, hi, lo);
                *(uint32_t*)(Ohi + rb + col) = hi;
                *(uint32_t*)(Olo + rb + col) = lo;
            }
        }
    }
}

// ---------------------------------------------------------------------------
// Attention: one block per (window, head), 64 threads = 64 query rows.
// ---------------------------------------------------------------------------
__global__ __launch_bounds__(64) void attn_k(
    const __nv_bfloat16* __restrict__ qh, const __nv_bfloat16* __restrict__ ql,
    const float* __restrict__ rpb_table, const int* __restrict__ rel_idx,
    const float* __restrict__ mask,
    __nv_bfloat16* __restrict__ oh, __nv_bfloat16* __restrict__ ol)
{
    const int blk = blockIdx.x;
    const int w   = blk / NH;
    const int hh  = blk % NH;
    const int t    = threadIdx.x;
    const int lane = t & 31;
    const int wrp  = t >> 5;

    __shared__ float Qs[64][33];
    __shared__ float Ks[64][33];
    __shared__ float Vs[64][33];

    const size_t rowbase = (size_t)w * 64;
    for (int j = wrp; j < 64; j += 2) {
        size_t base = (rowbase + j) * QKV_NP + hh * 32 + lane;
        Qs[j][lane] = rec(qh[base],       ql[base]);
        Ks[j][lane] = rec(qh[base + 192], ql[base + 192]);
        Vs[j][lane] = rec(qh[base + 384], ql[base + 384]);
    }
    __syncthreads();

    float q[32];
    #pragma unroll
    for (int d = 0; d < 32; d++) q[d] = Qs[t][d];

    float s[64];
    #pragma unroll
    for (int j = 0; j < 64; j++) {
        float a = 0.f;
        #pragma unroll
        for (int d = 0; d < 32; d++) a = fmaf(q[d], Ks[j][d], a);
        s[j] = a * SCALE_F;
    }

    const float* mrow = mask + ((w & 1023) * 4096 + t * 64);
    const int*   rrow = rel_idx + t * 64;
    float mx = -1e30f;
    #pragma unroll
    for (int j = 0; j < 64; j++) {
        s[j] += rpb_table[rrow[j] * NH + hh] + mrow[j];
        mx = fmaxf(mx, s[j]);
    }
    float sum = 0.f;
    #pragma unroll
    for (int j = 0; j < 64; j++) { s[j] = expf(s[j] - mx); sum += s[j]; }
    const float inv = 1.f / sum;

    float o[32] = {};
    #pragma unroll
    for (int j = 0; j < 64; j++) {
        float p = s[j] * inv;
        #pragma unroll
        for (int d = 0; d < 32; d++) o[d] = fmaf(p, Vs[j][d], o[d]);
    }

    size_t ob = (rowbase + t) * C_DIM + hh * 32;
    #pragma unroll
    for (int d = 0; d < 32; d += 2) {
        uint32_t hi, lo;
        split_pair2(o[d], o[d + 1], hi, lo);
        *(uint32_t*)(oh + ob + d) = hi;
        *(uint32_t*)(ol + ob + d) = lo;
    }
}

// ---------------------------------------------------------------------------
// LN1: x1 = res(fp32 x) + LN(y pair); out as pair
// ---------------------------------------------------------------------------
__global__ __launch_bounds__(256) void ln1_k(
    const __nv_bfloat16* __restrict__ yh, const __nv_bfloat16* __restrict__ yl,
    const float* __restrict__ resx,
    const float* __restrict__ g, const float* __restrict__ b,
    __nv_bfloat16* __restrict__ oh, __nv_bfloat16* __restrict__ ol)
{
    const size_t token = (size_t)blockIdx.x * 8 + (threadIdx.x >> 5);
    const int lane = threadIdx.x & 31;
    const size_t yb = token * C_DIM;

    float v[6];
    float sum = 0.f;
    #pragma unroll
    for (int i = 0; i < 6; i++) {
        int c = lane + 32 * i;
        v[i] = rec(yh[yb + c], yl[yb + c]);
        sum += v[i];
    }
    #pragma unroll
    for (int o = 16; o; o >>= 1) sum += __shfl_xor_sync(0xffffffffu, sum, o);
    const float mu = sum * (1.f / 192.f);
    float sq = 0.f;
    #pragma unroll
    for (int i = 0; i < 6; i++) { float d = v[i] - mu; sq = fmaf(d, d, sq); }
    #pragma unroll
    for (int o = 16; o; o >>= 1) sq += __shfl_xor_sync(0xffffffffu, sq, o);
    const float inv = rsqrtf(sq * (1.f / 192.f) + 1e-5f);

    #pragma unroll
    for (int i = 0; i < 6; i++) {
        int c = lane + 32 * i;
        float o = resx[yb + c] + (v[i] - mu) * inv * g[c] + b[c];
        __nv_bfloat16 h = __float2bfloat16_rn(o);
        oh[yb + c] = h;
        ol[yb + c] = __float2bfloat16_rn(o - __bfloat162float(h));
    }
}

// LN2: out(fp32) = res(pair x1) + LN(y pair)
__global__ __launch_bounds__(256) void ln2_k(
    const __nv_bfloat16* __restrict__ yh, const __nv_bfloat16* __restrict__ yl,
    const __nv_bfloat16* __restrict__ rh, const __nv_bfloat16* __restrict__ rl,
    const float* __restrict__ g, const float* __restrict__ b,
    float* __restrict__ outp)
{
    const size_t token = (size_t)blockIdx.x * 8 + (threadIdx.x >> 5);
    const int lane = threadIdx.x & 31;
    const size_t yb = token * C_DIM;

    float v[6];
    float sum = 0.f;
    #pragma unroll
    for (int i = 0; i < 6; i++) {
        int c = lane + 32 * i;
        v[i] = rec(yh[yb + c], yl[yb + c]);
        sum += v[i];
    }
    #pragma unroll
    for (int o = 16; o; o >>= 1) sum += __shfl_xor_sync(0xffffffffu, sum, o);
    const float mu = sum * (1.f / 192.f);
    float sq = 0.f;
    #pragma unroll
    for (int i = 0; i < 6; i++) { float d = v[i] - mu; sq = fmaf(d, d, sq); }
    #pragma unroll
    for (int o = 16; o; o >>= 1) sq += __shfl_xor_sync(0xffffffffu, sq, o);
    const float inv = rsqrtf(sq * (1.f / 192.f) + 1e-5f);

    #pragma unroll
    for (int i = 0; i < 6; i++) {
        int c = lane + 32 * i;
        outp[yb + c] = rec(rh[yb + c], rl[yb + c]) + (v[i] - mu) * inv * g[c] + b[c];
    }
}

// ---------------------------------------------------------------------------
// Launch
// ---------------------------------------------------------------------------
extern "C" void kernel_launch(void* const* d_in, const int* in_sizes, int n_in,
                              void* d_out, int out_size)
{
    const float* x      = (const float*)d_in[0];
    const float* mask   = (const float*)d_in[1];
    const int*   relidx = (const int*)  d_in[2];
    const float* qkv_w  = (const float*)d_in[3];
    const float* qkv_b  = (const float*)d_in[4];
    const float* proj_w = (const float*)d_in[5];
    const float* proj_b = (const float*)d_in[6];
    const float* rpb    = (const float*)d_in[7];
    const float* n1g    = (const float*)d_in[8];
    const float* n1b    = (const float*)d_in[9];
    const float* n2g    = (const float*)d_in[10];
    const float* n2b    = (const float*)d_in[11];
    const float* fc1w   = (const float*)d_in[12];
    const float* fc1b   = (const float*)d_in[13];
    const float* fc2w   = (const float*)d_in[14];
    const float* fc2b   = (const float*)d_in[15];
    float* out = (float*)d_out;

    char* pool;
    cudaGetSymbolAddress((void**)&pool, g_pool);
    __nv_bfloat16* qh  = (__nv_bfloat16*)(pool + OFF_Q);
    __nv_bfloat16* ql  = (__nv_bfloat16*)(pool + OFF_Q + SZ_QK);
    __nv_bfloat16* hh  = (__nv_bfloat16*)(pool + OFF_H);
    __nv_bfloat16* hl  = (__nv_bfloat16*)(pool + OFF_H + SZ_HI);
    __nv_bfloat16* xh  = (__nv_bfloat16*)(pool + OFF_X);
    __nv_bfloat16* xl  = (__nv_bfloat16*)(pool + OFF_X + SZ_CD);
    __nv_bfloat16* ah  = (__nv_bfloat16*)(pool + OFF_X);            // reuses x slot
    __nv_bfloat16* al  = (__nv_bfloat16*)(pool + OFF_X + SZ_CD);
    __nv_bfloat16* th  = (__nv_bfloat16*)(pool + OFF_T);
    __nv_bfloat16* tl  = (__nv_bfloat16*)(pool + OFF_T + SZ_CD);
    __nv_bfloat16* x1h = (__nv_bfloat16*)(pool + OFF_X1);
    __nv_bfloat16* x1l = (__nv_bfloat16*)(pool + OFF_X1 + SZ_CD);

    __nv_bfloat16 *wqh, *wql, *wph, *wpl, *w1h, *w1l, *w2h, *w2l;
    float* qb;
    cudaGetSymbolAddress((void**)&wqh, g_wqh); cudaGetSymbolAddress((void**)&wql, g_wql);
    cudaGetSymbolAddress((void**)&wph, g_wph); cudaGetSymbolAddress((void**)&wpl, g_wpl);
    cudaGetSymbolAddress((void**)&w1h, g_w1h); cudaGetSymbolAddress((void**)&w1l, g_w1l);
    cudaGetSymbolAddress((void**)&w2h, g_w2h); cudaGetSymbolAddress((void**)&w2l, g_w2l);
    cudaGetSymbolAddress((void**)&qb,  g_qb);

    constexpr int SM128 = NSTG * (2 * 128 * 80 + 2 * 128 * 80);   // 122880
    constexpr int SM64  = NSTG * (2 * 128 * 80 + 2 * 64 * 80);    // 92160
    cudaFuncSetAttribute(mm_split<128, false, false>, cudaFuncAttributeMaxDynamicSharedMemorySize, SM128);
    cudaFuncSetAttribute(mm_split<128, false, true >, cudaFuncAttributeMaxDynamicSharedMemorySize, SM128);
    cudaFuncSetAttribute(mm_split<64,  true,  false>, cudaFuncAttributeMaxDynamicSharedMemorySize, SM64);
    cudaFuncSetAttribute(mm_split<64,  false, false>, cudaFuncAttributeMaxDynamicSharedMemorySize, SM64);

    // 0. preps
    prep_w<<<(QKV_NP * (C_DIM / 4)) / 256, 256>>>(qkv_w, wqh, wql, QKV_NR, C_DIM);
    prep_w<<<(C_DIM  * (C_DIM / 4)) / 256, 256>>>(proj_w, wph, wpl, C_DIM, C_DIM);
    prep_w<<<(HIDDEN * (C_DIM / 4)) / 256, 256>>>(fc1w, w1h, w1l, HIDDEN, C_DIM);
    prep_w<<<(C_DIM  * (HIDDEN / 4)) / 256, 256>>>(fc2w, w2h, w2l, C_DIM, HIDDEN);
    prep_b<<<3, 256>>>(qkv_b, qb);
    prep_x<<<(M_TOT * 48) / 256, 256>>>(x, xh, xl);

    // 1. qkv GEMM (padded N=640)
    mm_split<128, false, false><<<dim3(QKV_NP / 128, M_TOT / BM), 256, SM128>>>(
        xh, xl, wqh, wql, qb, qh, ql, QKV_NP, C_DIM);

    // 2. windowed attention
    attn_k<<<NWIN * NH, 64>>>(qh, ql, rpb, relidx, mask, ah, al);

    // 3. proj GEMM + scatter to image layout
    mm_split<64, true, false><<<dim3(C_DIM / 64, M_TOT / BM), 256, SM64>>>(
        ah, al, wph, wpl, proj_b, th, tl, C_DIM, C_DIM);

    // 4. x1 = x + LN1(proj_img)
    ln1_k<<<M_TOT / 8, 256>>>(th, tl, x, n1g, n1b, x1h, x1l);

    // 5. fc1 + GELU
    mm_split<128, false, true><<<dim3(HIDDEN / 128, M_TOT / BM), 256, SM128>>>(
        x1h, x1l, w1h, w1l, fc1b, hh, hl, HIDDEN, C_DIM);

    // 6. fc2
    mm_split<64, false, false><<<dim3(C_DIM / 64, M_TOT / BM), 256, SM64>>>(
        hh, hl, w2h, w2l, fc2b, th, tl, C_DIM, HIDDEN);

    // 7. out = x1 + LN2(fc2_out)
    ln2_k<<<M_TOT / 8, 256>>>(th, tl, x1h, x1l, n2g, n2b, out);
}

// round 7
// speedup vs baseline: 1.2551x; 1.2551x over previous
#include <cuda_runtime.h>
#include <cuda_fp16.h>
#include <math.h>
#include <stdint.h>

// ---------------------------------------------------------------------------
#define C_DIM   192
#define NH      6
#define NWIN    4096
#define M_TOT   262144
#define HIDDEN  768
#define QKV_NP  640          // padded qkv output cols
#define QKV_NR  576
#define SCALE_F 0.17677669529663687f

// ---------------------------------------------------------------------------
// Shared scratch pool, time-disjoint offsets (same layout as R6; planes are
// fp16 now, same byte sizes). Pool = 1.31 GiB < 2 GB reloc limit.
// ---------------------------------------------------------------------------
#define SZ_CD  ((size_t)M_TOT * C_DIM * 2)
#define SZ_QK  ((size_t)M_TOT * QKV_NP * 2)
#define SZ_HI  ((size_t)M_TOT * HIDDEN * 2)
#define OFF_Q  ((size_t)0)
#define OFF_H  ((size_t)0)
#define OFF_X  (2 * SZ_QK + SZ_CD + (size_t)33554432)
#define OFF_T  (OFF_X + 2 * SZ_CD)
#define OFF_X1 (OFF_T + 2 * SZ_CD)
#define POOLSZ (OFF_X1 + 2 * SZ_CD)

__device__ __align__(256) char g_pool[POOLSZ];

__device__ __half g_wq[QKV_NP * C_DIM];
__device__ __half g_wp[C_DIM * C_DIM];
__device__ __half g_w1[HIDDEN * C_DIM];
__device__ __half g_w2[C_DIM * HIDDEN];
__device__ float  g_qb [QKV_NP];
__device__ float  g_rpbd[NH * 64 * 64];

// ---------------------------------------------------------------------------
__device__ __forceinline__ int map_row(int m) {
    int w    = m >> 6;
    int t    = m & 63;
    int b    = w >> 10;
    int widx = w & 1023;
    int wh   = widx >> 5;
    int ww   = widx & 31;
    int r    = t >> 3;
    int c    = t & 7;
    int h    = (wh * 8 + r + 4) & 255;
    int wc   = (ww * 8 + c + 4) & 255;
    return (b << 16) | (h << 8) | wc;
}

__device__ __forceinline__ uint32_t smem_to_u32(const void* p) {
    uint32_t a;
    asm("{ .reg .u64 t; cvta.to.shared.u64 t, %1; cvt.u32.u64 %0, t; }" : "=r"(a) : "l"(p));
    return a;
}

#define CP_ASYNC16(dst, src) \
    asm volatile("cp.async.cg.shared.global [%0], [%1], 16;" :: "r"(dst), "l"(src))
#define CP_COMMIT() asm volatile("cp.async.commit_group;")
#define CP_WAIT(n)  asm volatile("cp.async.wait_group %0;" :: "n"(n))

#define LDM_X4(r0, r1, r2, r3, addr) \
    asm volatile("ldmatrix.sync.aligned.m8n8.x4.shared.b16 {%0,%1,%2,%3}, [%4];" \
                 : "=r"(r0), "=r"(r1), "=r"(r2), "=r"(r3) : "r"(addr))

#define MMA_F16(d, a, b) \
    asm volatile("mma.sync.aligned.m16n8k16.row.col.f32.f16.f16.f32 " \
                 "{%0,%1,%2,%3}, {%4,%5,%6,%7}, {%8,%9}, {%0,%1,%2,%3};" \
                 : "+f"((d)[0]), "+f"((d)[1]), "+f"((d)[2]), "+f"((d)[3]) \
                 : "r"((a)[0]), "r"((a)[1]), "r"((a)[2]), "r"((a)[3]), \
                   "r"((b)[0]), "r"((b)[1]))

__device__ __forceinline__ uint32_t pk_h2(float x, float y) {
    __half2 t = __floats2half2_rn(x, y);
    return *(uint32_t*)&t;
}
// fp16 split: hi = rn(v), lo = rn(v - hi); ~22 combined mantissa bits
__device__ __forceinline__ void split_h2(float x, float y, uint32_t& hi, uint32_t& lo) {
    __half hx = __float2half_rn(x);
    __half hy = __float2half_rn(y);
    hi = (uint32_t)__half_as_ushort(hx) | ((uint32_t)__half_as_ushort(hy) << 16);
    lo = pk_h2(x - __half2float(hx), y - __half2float(hy));
}
__device__ __forceinline__ float rec(const __half h, const __half l) {
    return __half2float(h) + __half2float(l);
}

// ---------------------------------------------------------------------------
// Prep kernels
// ---------------------------------------------------------------------------
__global__ __launch_bounds__(256) void prep_x(
    const float* __restrict__ x, __half* __restrict__ xh, __half* __restrict__ xl)
{
    int idx = blockIdx.x * 256 + threadIdx.x;      // M_TOT * 48
    int m = idx / 48, c4 = idx % 48;
    float4 v = *(const float4*)(x + (size_t)map_row(m) * C_DIM + c4 * 4);
    uint32_t h0, l0, h1, l1;
    split_h2(v.x, v.y, h0, l0);
    split_h2(v.z, v.w, h1, l1);
    size_t o = (size_t)m * C_DIM + c4 * 4;
    *(uint2*)(xh + o) = make_uint2(h0, h1);
    *(uint2*)(xl + o) = make_uint2(l0, l1);
}

// weight fp32 [rows][K] -> single fp16 plane [padRows][K] (zero pad rows)
__global__ __launch_bounds__(256) void prep_w(
    const float* __restrict__ w, __half* __restrict__ wo, int rows, int K)
{
    int idx = blockIdx.x * 256 + threadIdx.x;      // padRows * K/4
    int k4 = K / 4;
    int row = idx / k4, c4 = idx % k4;
    float4 v = make_float4(0.f, 0.f, 0.f, 0.f);
    if (row < rows) v = *(const float4*)(w + (size_t)row * K + c4 * 4);
    size_t o = (size_t)row * K + c4 * 4;
    *(uint2*)(wo + o) = make_uint2(pk_h2(v.x, v.y), pk_h2(v.z, v.w));
}

__global__ void prep_b(const float* __restrict__ b, float* __restrict__ bp) {
    int i = blockIdx.x * 256 + threadIdx.x;
    if (i < QKV_NP) bp[i] = (i < QKV_NR) ? b[i] : 0.f;
}

// dense relative-position-bias table: rpbd[h][t][j]
__global__ void prep_rpb(const float* __restrict__ rpb_table, const int* __restrict__ rel_idx,
                         float* __restrict__ rpbd)
{
    int idx = blockIdx.x * 256 + threadIdx.x;      // NH*4096
    int h = idx >> 12, tj = idx & 4095;
    rpbd[idx] = rpb_table[rel_idx[tj] * NH + h];
}

// ---------------------------------------------------------------------------
// fp16 2-term HMMA GEMM with cp.async 3-stage pipeline.
// C[m,n] = sum_k A[m,k] W[n,k] + bias[n]; A pre-split fp16 hi/lo, W fp16.
// BM=128, BK=32, BNT in {64,128}. 256 threads, warps 4(M) x 2(N).
// ---------------------------------------------------------------------------
#define BM   128
#define BK   32
#define NSTG 3

template<int BNT, bool SCATTER, bool DOGELU>
__global__ __launch_bounds__(256, 2) void mm_split(
    const __half* __restrict__ Ah, const __half* __restrict__ Al,
    const __half* __restrict__ Wp,
    const float* __restrict__ bias,
    __half* __restrict__ Ohi, __half* __restrict__ Olo,
    int N, int K)
{
    constexpr int ATB  = 128 * 80;                 // bytes per A plane tile
    constexpr int BTB  = BNT * 80;
    constexpr int SST_ = 2 * ATB + BTB;            // stage bytes (3 planes)
    constexpr int WN   = BNT / 2;
    constexpr int NT8  = WN / 8;
    constexpr int NT2  = WN / 16;
    constexpr int BCH  = (BNT == 128) ? 2 : 1;

    extern __shared__ char sm[];
    const uint32_t sbase = smem_to_u32(sm);

    const int tid = threadIdx.x, wid = tid >> 5, lane = tid & 31;
    const int warpM = wid & 3, warpN = wid >> 2;
    const int rowBase = blockIdx.y * BM;
    const int colBase = blockIdx.x * BNT;
    const int nch = K / BK;

    // staging descriptors (16B chunks; 4 per 64B k-row-slice)
    const __half* aSrcH[2]; const __half* aSrcL[2];
    uint32_t aDst[2];
    #pragma unroll
    for (int t = 0; t < 2; t++) {
        int cidx = tid + t * 256;
        int row = cidx >> 2, kc = cidx & 3;
        size_t go = (size_t)(rowBase + row) * K + kc * 8;
        aSrcH[t] = Ah + go; aSrcL[t] = Al + go;
        aDst[t] = row * 80 + kc * 16;
    }
    const __half* bSrc[BCH];
    uint32_t bDst[BCH];
    #pragma unroll
    for (int t = 0; t < BCH; t++) {
        int cidx = tid + t * 256;
        int row = cidx >> 2, kc = cidx & 3;
        bSrc[t] = Wp + (size_t)(colBase + row) * K + kc * 8;
        bDst[t] = row * 80 + kc * 16;
    }

    auto issue = [&](int s, int it) {
        uint32_t sb = sbase + s * SST_;
        int k0 = it * BK;
        #pragma unroll
        for (int t = 0; t < 2; t++) {
            CP_ASYNC16(sb + aDst[t],       aSrcH[t] + k0);
            CP_ASYNC16(sb + ATB + aDst[t], aSrcL[t] + k0);
        }
        #pragma unroll
        for (int t = 0; t < BCH; t++)
            CP_ASYNC16(sb + 2 * ATB + bDst[t], bSrc[t] + k0);
        CP_COMMIT();
    };

    // ldmatrix coordinates
    const uint32_t aRowL = (uint32_t)(warpM * 32 + (lane & 15));
    const uint32_t aColB = (uint32_t)(((lane >> 4) * 8) * 2);
    const uint32_t bRowL = (uint32_t)(warpN * WN + (lane & 7) + ((lane >> 4) << 3));
    const uint32_t bColB = (uint32_t)((((lane >> 3) & 1) * 8) * 2);

    float acc[2][NT8][4] = {};

    issue(0, 0);
    issue(1, 1);

    for (int it = 0; it < nch; it++) {
        CP_WAIT(1);
        __syncthreads();
        const uint32_t stg = sbase + (it % NSTG) * SST_;

        #pragma unroll
        for (int kk = 0; kk < BK; kk += 16) {
            uint32_t ah[2][4], al[2][4], bb[NT2][4];
            #pragma unroll
            for (int mt = 0; mt < 2; mt++) {
                uint32_t off = (aRowL + mt * 16) * 80 + aColB + kk * 2;
                LDM_X4(ah[mt][0], ah[mt][1], ah[mt][2], ah[mt][3], stg + off);
                LDM_X4(al[mt][0], al[mt][1], al[mt][2], al[mt][3], stg + ATB + off);
            }
            #pragma unroll
            for (int nt2 = 0; nt2 < NT2; nt2++) {
                uint32_t off = 2 * ATB + (bRowL + nt2 * 16) * 80 + bColB + kk * 2;
                LDM_X4(bb[nt2][0], bb[nt2][1], bb[nt2][2], bb[nt2][3], stg + off);
            }
            #pragma unroll
            for (int mt = 0; mt < 2; mt++) {
                #pragma unroll
                for (int n = 0; n < NT8; n++) {
                    uint32_t bf[2] = { bb[n >> 1][(n & 1) * 2], bb[n >> 1][(n & 1) * 2 + 1] };
                    MMA_F16(acc[mt][n], ah[mt], bf);
                    MMA_F16(acc[mt][n], al[mt], bf);
                }
            }
        }

        int nxt = it + NSTG - 1;
        if (nxt < nch) issue(nxt % NSTG, nxt);
        else           CP_COMMIT();
    }

    // ---- epilogue: split + store hi/lo ----
    const int qid = lane >> 2;
    const int cid2 = (lane & 3) * 2;
    #pragma unroll
    for (int mt = 0; mt < 2; mt++) {
        #pragma unroll
        for (int hf = 0; hf < 2; hf++) {
            int row = rowBase + warpM * 32 + mt * 16 + qid + hf * 8;
            if (SCATTER) row = map_row(row);
            size_t rb = (size_t)row * N;
            #pragma unroll
            for (int n = 0; n < NT8; n++) {
                int col = colBase + warpN * WN + n * 8 + cid2;
                float2 bv = *(const float2*)(bias + col);
                float ox = acc[mt][n][hf * 2 + 0] + bv.x;
                float oy = acc[mt][n][hf * 2 + 1] + bv.y;
                if (DOGELU) {
                    ox = 0.5f * ox * (1.0f + erff(ox * 0.70710678118654752f));
                    oy = 0.5f * oy * (1.0f + erff(oy * 0.70710678118654752f));
                }
                uint32_t hi, lo;
                split_h2(ox, oy, hi, lo);
                *(uint32_t*)(Ohi + rb + col) = hi;
                *(uint32_t*)(Olo + rb + col) = lo;
            }
        }
    }
}

// ---------------------------------------------------------------------------
// Attention: one block per (window, head), 64 threads = 64 query rows.
// ---------------------------------------------------------------------------
__global__ __launch_bounds__(64) void attn_k(
    const __half* __restrict__ qh, const __half* __restrict__ ql,
    const float* __restrict__ rpbd, const float* __restrict__ mask,
    __half* __restrict__ oh, __half* __restrict__ ol)
{
    const int blk = blockIdx.x;
    const int w   = blk / NH;
    const int hh  = blk % NH;
    const int t    = threadIdx.x;
    const int lane = t & 31;
    const int wrp  = t >> 5;

    __shared__ float Qs[64][33];
    __shared__ float Ks[64][33];
    __shared__ float Vs[64][33];

    const size_t rowbase = (size_t)w * 64;
    for (int j = wrp; j < 64; j += 2) {
        size_t base = (rowbase + j) * QKV_NP + hh * 32 + lane;
        Qs[j][lane] = rec(qh[base],       ql[base]);
        Ks[j][lane] = rec(qh[base + 192], ql[base + 192]);
        Vs[j][lane] = rec(qh[base + 384], ql[base + 384]);
    }
    __syncthreads();

    float q[32];
    #pragma unroll
    for (int d = 0; d < 32; d++) q[d] = Qs[t][d];

    float s[64];
    #pragma unroll
    for (int j = 0; j < 64; j++) {
        float a = 0.f;
        #pragma unroll
        for (int d = 0; d < 32; d++) a = fmaf(q[d], Ks[j][d], a);
        s[j] = a * SCALE_F;
    }

    const float* mrow = mask + ((w & 1023) * 4096 + t * 64);
    const float* rrow = rpbd + hh * 4096 + t * 64;
    float mx = -1e30f;
    #pragma unroll
    for (int j = 0; j < 64; j++) {
        s[j] += rrow[j] + mrow[j];
        mx = fmaxf(mx, s[j]);
    }
    float sum = 0.f;
    #pragma unroll
    for (int j = 0; j < 64; j++) { s[j] = expf(s[j] - mx); sum += s[j]; }
    const float inv = 1.f / sum;

    float o[32] = {};
    #pragma unroll
    for (int j = 0; j < 64; j++) {
        float p = s[j] * inv;
        #pragma unroll
        for (int d = 0; d < 32; d++) o[d] = fmaf(p, Vs[j][d], o[d]);
    }

    size_t ob = (rowbase + t) * C_DIM + hh * 32;
    #pragma unroll
    for (int d = 0; d < 32; d += 2) {
        uint32_t hi, lo;
        split_h2(o[d], o[d + 1], hi, lo);
        *(uint32_t*)(oh + ob + d) = hi;
        *(uint32_t*)(ol + ob + d) = lo;
    }
}

// ---------------------------------------------------------------------------
// LN1: x1 = res(fp32 x, image layout) + LN(y pair); out pair
// ---------------------------------------------------------------------------
__global__ __launch_bounds__(256) void ln1_k(
    const __half* __restrict__ yh, const __half* __restrict__ yl,
    const float* __restrict__ resx,
    const float* __restrict__ g, const float* __restrict__ b,
    __half* __restrict__ oh, __half* __restrict__ ol)
{
    const size_t token = (size_t)blockIdx.x * 8 + (threadIdx.x >> 5);
    const int lane = threadIdx.x & 31;
    const size_t yb = token * C_DIM;

    float v[6];
    float sum = 0.f;
    #pragma unroll
    for (int i = 0; i < 6; i++) {
        int c = lane + 32 * i;
        v[i] = rec(yh[yb + c], yl[yb + c]);
        sum += v[i];
    }
    #pragma unroll
    for (int o = 16; o; o >>= 1) sum += __shfl_xor_sync(0xffffffffu, sum, o);
    const float mu = sum * (1.f / 192.f);
    float sq = 0.f;
    #pragma unroll
    for (int i = 0; i < 6; i++) { float d = v[i] - mu; sq = fmaf(d, d, sq); }
    #pragma unroll
    for (int o = 16; o; o >>= 1) sq += __shfl_xor_sync(0xffffffffu, sq, o);
    const float inv = rsqrtf(sq * (1.f / 192.f) + 1e-5f);

    #pragma unroll
    for (int i = 0; i < 6; i++) {
        int c = lane + 32 * i;
        float o = resx[yb + c] + (v[i] - mu) * inv * g[c] + b[c];
        __half h = __float2half_rn(o);
        oh[yb + c] = h;
        ol[yb + c] = __float2half_rn(o - __half2float(h));
    }
}

// LN2: out(fp32) = res(pair x1) + LN(y pair)
__global__ __launch_bounds__(256) void ln2_k(
    const __half* __restrict__ yh, const __half* __restrict__ yl,
    const __half* __restrict__ rh, const __half* __restrict__ rl,
    const float* __restrict__ g, const float* __restrict__ b,
    float* __restrict__ outp)
{
    const size_t token = (size_t)blockIdx.x * 8 + (threadIdx.x >> 5);
    const int lane = threadIdx.x & 31;
    const size_t yb = token * C_DIM;

    float v[6];
    float sum = 0.f;
    #pragma unroll
    for (int i = 0; i < 6; i++) {
        int c = lane + 32 * i;
        v[i] = rec(yh[yb + c], yl[yb + c]);
        sum += v[i];
    }
    #pragma unroll
    for (int o = 16; o; o >>= 1) sum += __shfl_xor_sync(0xffffffffu, sum, o);
    const float mu = sum * (1.f / 192.f);
    float sq = 0.f;
    #pragma unroll
    for (int i = 0; i < 6; i++) { float d = v[i] - mu; sq = fmaf(d, d, sq); }
    #pragma unroll
    for (int o = 16; o; o >>= 1) sq += __shfl_xor_sync(0xffffffffu, sq, o);
    const float inv = rsqrtf(sq * (1.f / 192.f) + 1e-5f);

    #pragma unroll
    for (int i = 0; i < 6; i++) {
        int c = lane + 32 * i;
        outp[yb + c] = rec(rh[yb + c], rl[yb + c]) + (v[i] - mu) * inv * g[c] + b[c];
    }
}

// ---------------------------------------------------------------------------
// Launch
// ---------------------------------------------------------------------------
extern "C" void kernel_launch(void* const* d_in, const int* in_sizes, int n_in,
                              void* d_out, int out_size)
{
    const float* x      = (const float*)d_in[0];
    const float* mask   = (const float*)d_in[1];
    const int*   relidx = (const int*)  d_in[2];
    const float* qkv_w  = (const float*)d_in[3];
    const float* qkv_b  = (const float*)d_in[4];
    const float* proj_w = (const float*)d_in[5];
    const float* proj_b = (const float*)d_in[6];
    const float* rpb    = (const float*)d_in[7];
    const float* n1g    = (const float*)d_in[8];
    const float* n1b    = (const float*)d_in[9];
    const float* n2g    = (const float*)d_in[10];
    const float* n2b    = (const float*)d_in[11];
    const float* fc1w   = (const float*)d_in[12];
    const float* fc1b   = (const float*)d_in[13];
    const float* fc2w   = (const float*)d_in[14];
    const float* fc2b   = (const float*)d_in[15];
    float* out = (float*)d_out;

    char* pool;
    cudaGetSymbolAddress((void**)&pool, g_pool);
    __half* qh  = (__half*)(pool + OFF_Q);
    __half* ql  = (__half*)(pool + OFF_Q + SZ_QK);
    __half* hh  = (__half*)(pool + OFF_H);
    __half* hl  = (__half*)(pool + OFF_H + SZ_HI);
    __half* xh  = (__half*)(pool + OFF_X);
    __half* xl  = (__half*)(pool + OFF_X + SZ_CD);
    __half* ah  = (__half*)(pool + OFF_X);            // reuses x slot
    __half* al  = (__half*)(pool + OFF_X + SZ_CD);
    __half* th  = (__half*)(pool + OFF_T);
    __half* tl  = (__half*)(pool + OFF_T + SZ_CD);
    __half* x1h = (__half*)(pool + OFF_X1);
    __half* x1l = (__half*)(pool + OFF_X1 + SZ_CD);

    __half *wq, *wp, *w1, *w2;
    float *qb, *rpbd;
    cudaGetSymbolAddress((void**)&wq, g_wq);
    cudaGetSymbolAddress((void**)&wp, g_wp);
    cudaGetSymbolAddress((void**)&w1, g_w1);
    cudaGetSymbolAddress((void**)&w2, g_w2);
    cudaGetSymbolAddress((void**)&qb, g_qb);
    cudaGetSymbolAddress((void**)&rpbd, g_rpbd);

    constexpr int SM128 = NSTG * (2 * 128 * 80 + 128 * 80);   // 92160
    constexpr int SM64  = NSTG * (2 * 128 * 80 + 64 * 80);    // 76800
    cudaFuncSetAttribute(mm_split<128, false, false>, cudaFuncAttributeMaxDynamicSharedMemorySize, SM128);
    cudaFuncSetAttribute(mm_split<128, false, true >, cudaFuncAttributeMaxDynamicSharedMemorySize, SM128);
    cudaFuncSetAttribute(mm_split<64,  true,  false>, cudaFuncAttributeMaxDynamicSharedMemorySize, SM64);
    cudaFuncSetAttribute(mm_split<64,  false, false>, cudaFuncAttributeMaxDynamicSharedMemorySize, SM64);

    // 0. preps
    prep_w<<<(QKV_NP * (C_DIM / 4)) / 256, 256>>>(qkv_w, wq, QKV_NR, C_DIM);
    prep_w<<<(C_DIM  * (C_DIM / 4)) / 256, 256>>>(proj_w, wp, C_DIM, C_DIM);
    prep_w<<<(HIDDEN * (C_DIM / 4)) / 256, 256>>>(fc1w, w1, HIDDEN, C_DIM);
    prep_w<<<(C_DIM  * (HIDDEN / 4)) / 256, 256>>>(fc2w, w2, C_DIM, HIDDEN);
    prep_b<<<3, 256>>>(qkv_b, qb);
    prep_rpb<<<(NH * 4096) / 256, 256>>>(rpb, relidx, rpbd);
    prep_x<<<(M_TOT * 48) / 256, 256>>>(x, xh, xl);

    // 1. qkv GEMM (padded N=640)
    mm_split<128, false, false><<<dim3(QKV_NP / 128, M_TOT / BM), 256, SM128>>>(
        xh, xl, wq, qb, qh, ql, QKV_NP, C_DIM);

    // 2. windowed attention
    attn_k<<<NWIN * NH, 64>>>(qh, ql, rpbd, mask, ah, al);

    // 3. proj GEMM + scatter to image layout
    mm_split<64, true, false><<<dim3(C_DIM / 64, M_TOT / BM), 256, SM64>>>(
        ah, al, wp, proj_b, th, tl, C_DIM, C_DIM);

    // 4. x1 = x + LN1(proj_img)
    ln1_k<<<M_TOT / 8, 256>>>(th, tl, x, n1g, n1b, x1h, x1l);

    // 5. fc1 + GELU
    mm_split<128, false, true><<<dim3(HIDDEN / 128, M_TOT / BM), 256, SM128>>>(
        x1h, x1l, w1, fc1b, hh, hl, HIDDEN, C_DIM);

    // 6. fc2
    mm_split<64, false, false><<<dim3(C_DIM / 64, M_TOT / BM), 256, SM64>>>(
        hh, hl, w2, fc2b, th, tl, C_DIM, HIDDEN);

    // 7. out = x1 + LN2(fc2_out)
    ln2_k<<<M_TOT / 8, 256>>>(th, tl, x1h, x1l, n2g, n2b, out);
}

// round 8
// speedup vs baseline: 1.3931x; 1.1100x over previous
#include <cuda_runtime.h>
#include <cuda_fp16.h>
#include <math.h>
#include <stdint.h>

// ---------------------------------------------------------------------------
#define C_DIM   192
#define NH      6
#define NWIN    4096
#define M_TOT   262144
#define HIDDEN  768
#define QKV_N   576
#define SCALE_F 0.17677669529663687f

// K' (halves) = 2 * logical K for activations (interleaved hi/lo)
#define KP_CD   384          // 2*192
#define KP_HI   1536         // 2*768
#define NP_QKV  1152         // 2*576  (halves stride of qkv rows)

// ---------------------------------------------------------------------------
// Shared scratch pool (time-disjoint offsets), all activations interleaved
// (hi,lo) fp16 pairs: 4 bytes per logical element.
//   q  [0, 604MB)           live: qkv gemm -> attention
//   h  [0, 805MB)           live: fc1 -> fc2            (overlaps q)
//   x/a[805MB, +201MB)      x: prep->qkv;  a: attn->proj (disjoint in time)
//   t  [+201MB)             proj->ln1, fc2->ln2
//   x1 [+201MB)             ln1 -> ln2
// ---------------------------------------------------------------------------
#define SZ_CD  ((size_t)M_TOT * KP_CD * 2)           // 201,326,592
#define OFF_X  ((size_t)805306368)
#define OFF_T  (OFF_X + SZ_CD)
#define OFF_X1 (OFF_T + SZ_CD)
#define POOLSZ (OFF_X1 + SZ_CD)                      // 1,409,286,144

__device__ __align__(256) char g_pool[POOLSZ];

__device__ __half g_wq[QKV_N * KP_CD];               // duplicated-k fp16 weights
__device__ __half g_wp[C_DIM * KP_CD];
__device__ __half g_w1[HIDDEN * KP_CD];
__device__ __half g_w2[C_DIM * KP_HI];
__device__ float  g_rpbd[NH * 64 * 64];

// ---------------------------------------------------------------------------
__device__ __forceinline__ int map_row(int m) {
    int w    = m >> 6;
    int t    = m & 63;
    int b    = w >> 10;
    int widx = w & 1023;
    int wh   = widx >> 5;
    int ww   = widx & 31;
    int r    = t >> 3;
    int c    = t & 7;
    int h    = (wh * 8 + r + 4) & 255;
    int wc   = (ww * 8 + c + 4) & 255;
    return (b << 16) | (h << 8) | wc;
}

__device__ __forceinline__ uint32_t smem_to_u32(const void* p) {
    uint32_t a;
    asm("{ .reg .u64 t; cvta.to.shared.u64 t, %1; cvt.u32.u64 %0, t; }" : "=r"(a) : "l"(p));
    return a;
}

#define CP_ASYNC16(dst, src) \
    asm volatile("cp.async.cg.shared.global [%0], [%1], 16;" :: "r"(dst), "l"(src))
#define CP_COMMIT() asm volatile("cp.async.commit_group;")
#define CP_WAIT(n)  asm volatile("cp.async.wait_group %0;" :: "n"(n))

#define LDM_X4(r0, r1, r2, r3, addr) \
    asm volatile("ldmatrix.sync.aligned.m8n8.x4.shared.b16 {%0,%1,%2,%3}, [%4];" \
                 : "=r"(r0), "=r"(r1), "=r"(r2), "=r"(r3) : "r"(addr))

#define MMA_F16(d, a, b) \
    asm volatile("mma.sync.aligned.m16n8k16.row.col.f32.f16.f16.f32 " \
                 "{%0,%1,%2,%3}, {%4,%5,%6,%7}, {%8,%9}, {%0,%1,%2,%3};" \
                 : "+f"((d)[0]), "+f"((d)[1]), "+f"((d)[2]), "+f"((d)[3]) \
                 : "r"((a)[0]), "r"((a)[1]), "r"((a)[2]), "r"((a)[3]), \
                   "r"((b)[0]), "r"((b)[1]))

// interleaved pack: one fp32 -> uint32 (hi fp16 low half, residual lo fp16 high)
__device__ __forceinline__ uint32_t ipack(float v) {
    __half h = __float2half_rn(v);
    __half l = __float2half_rn(v - __half2float(h));
    return (uint32_t)__half_as_ushort(h) | ((uint32_t)__half_as_ushort(l) << 16);
}
__device__ __forceinline__ float iunpack(uint32_t u) {
    __half h = __ushort_as_half((unsigned short)(u & 0xffff));
    __half l = __ushort_as_half((unsigned short)(u >> 16));
    return __half2float(h) + __half2float(l);
}
// duplicate one fp16 into both halves (for weights)
__device__ __forceinline__ uint32_t wdup(float v) {
    uint32_t h = (uint32_t)__half_as_ushort(__float2half_rn(v));
    return h | (h << 16);
}

// ---------------------------------------------------------------------------
// Prep kernels
// ---------------------------------------------------------------------------
__global__ __launch_bounds__(256) void prep_x(
    const float* __restrict__ x, uint32_t* __restrict__ xo)
{
    int idx = blockIdx.x * 256 + threadIdx.x;      // M_TOT * 48
    int m = idx / 48, c4 = idx % 48;
    float4 v = *(const float4*)(x + (size_t)map_row(m) * C_DIM + c4 * 4);
    uint4 o = make_uint4(ipack(v.x), ipack(v.y), ipack(v.z), ipack(v.w));
    *(uint4*)(xo + (size_t)m * C_DIM + c4 * 4) = o;
}

// weight fp32 [rows][K] -> fp16 dup-k [rows][2K]
__global__ __launch_bounds__(256) void prep_w(
    const float* __restrict__ w, uint32_t* __restrict__ wo, int K)
{
    int idx = blockIdx.x * 256 + threadIdx.x;      // rows * K/4
    int k4 = K / 4;
    int row = idx / k4, c4 = idx % k4;
    float4 v = *(const float4*)(w + (size_t)row * K + c4 * 4);
    uint4 o = make_uint4(wdup(v.x), wdup(v.y), wdup(v.z), wdup(v.w));
    *(uint4*)(wo + (size_t)row * K + c4 * 4) = o;   // uint32 per logical k
}

__global__ void prep_rpb(const float* __restrict__ rpb_table, const int* __restrict__ rel_idx,
                         float* __restrict__ rpbd)
{
    int idx = blockIdx.x * 256 + threadIdx.x;      // NH*4096
    int h = idx >> 12, tj = idx & 4095;
    rpbd[idx] = rpb_table[rel_idx[tj] * NH + h];
}

// ---------------------------------------------------------------------------
// Plain fp16 HMMA GEMM over K' (interleaved A, dup-k W), cp.async 3-stage.
// logical C[m,n] = sum A(m,k) W(n,k) + bias[n].
// BM=128, BN=64, BK'=64 halves. 256 threads, warps 4(M) x 2(N), tile 32x32.
// ---------------------------------------------------------------------------
#define BM   128
#define BKH  64              // K' halves per chunk
#define RS   144             // smem row stride bytes (128 data + 16 pad)
#define ATB  (128 * RS)      // 18432
#define BTB  (64 * RS)       // 9216
#define SSTG (ATB + BTB)     // 27648
#define NSTG 3
#define MMSMEM (NSTG * SSTG) // 82944

template<bool SCATTER, bool DOGELU>
__global__ __launch_bounds__(256, 2) void mm_i(
    const __half* __restrict__ A, const __half* __restrict__ W,
    const float* __restrict__ bias, uint32_t* __restrict__ Ou,
    float* __restrict__ Of,            // exactly one of Ou/Of is used
    int N, int Kp)
{
    extern __shared__ char sm[];
    const uint32_t sbase = smem_to_u32(sm);

    const int tid = threadIdx.x, wid = tid >> 5, lane = tid & 31;
    const int warpM = wid & 3, warpN = wid >> 2;
    const int rowBase = blockIdx.y * BM;
    const int colBase = blockIdx.x * 64;
    const int nch = Kp / BKH;

    // staging: A 1024 16B-chunks (4/thread), B 512 (2/thread)
    const __half* aSrc[4]; uint32_t aDst[4];
    #pragma unroll
    for (int t = 0; t < 4; t++) {
        int idx = tid + t * 256;
        int row = idx >> 3, kc = idx & 7;
        aSrc[t] = A + (size_t)(rowBase + row) * Kp + kc * 8;
        aDst[t] = row * RS + kc * 16;
    }
    const __half* bSrc[2]; uint32_t bDst[2];
    #pragma unroll
    for (int t = 0; t < 2; t++) {
        int idx = tid + t * 256;
        int row = idx >> 3, kc = idx & 7;
        bSrc[t] = W + (size_t)(colBase + row) * Kp + kc * 8;
        bDst[t] = ATB + row * RS + kc * 16;
    }

    auto issue = [&](int s, int it) {
        uint32_t sb = sbase + s * SSTG;
        int k0 = it * BKH;
        #pragma unroll
        for (int t = 0; t < 4; t++) CP_ASYNC16(sb + aDst[t], aSrc[t] + k0);
        #pragma unroll
        for (int t = 0; t < 2; t++) CP_ASYNC16(sb + bDst[t], bSrc[t] + k0);
        CP_COMMIT();
    };

    const uint32_t aRowL = (uint32_t)(warpM * 32 + (lane & 15));
    const uint32_t aColB = (uint32_t)(((lane >> 4) * 8) * 2);
    const uint32_t bRowL = (uint32_t)(warpN * 32 + (lane & 7) + ((lane >> 4) << 3));
    const uint32_t bColB = (uint32_t)((((lane >> 3) & 1) * 8) * 2);

    float acc[2][4][4] = {};

    issue(0, 0);
    issue(1, 1);

    for (int it = 0; it < nch; it++) {
        CP_WAIT(1);
        __syncthreads();
        const uint32_t stg = sbase + (it % NSTG) * SSTG;

        #pragma unroll
        for (int kk = 0; kk < BKH; kk += 16) {
            uint32_t ah[2][4], bb[2][4];
            #pragma unroll
            for (int mt = 0; mt < 2; mt++) {
                uint32_t off = (aRowL + mt * 16) * RS + aColB + kk * 2;
                LDM_X4(ah[mt][0], ah[mt][1], ah[mt][2], ah[mt][3], stg + off);
            }
            #pragma unroll
            for (int nt2 = 0; nt2 < 2; nt2++) {
                uint32_t off = ATB + (bRowL + nt2 * 16) * RS + bColB + kk * 2;
                LDM_X4(bb[nt2][0], bb[nt2][1], bb[nt2][2], bb[nt2][3], stg + off);
            }
            #pragma unroll
            for (int mt = 0; mt < 2; mt++) {
                #pragma unroll
                for (int n = 0; n < 4; n++) {
                    uint32_t bf[2] = { bb[n >> 1][(n & 1) * 2], bb[n >> 1][(n & 1) * 2 + 1] };
                    MMA_F16(acc[mt][n], ah[mt], bf);
                }
            }
        }

        int nxt = it + NSTG - 1;
        if (nxt < nch) issue(nxt % NSTG, nxt);
        else           CP_COMMIT();
    }

    // ---- epilogue ----
    const int qid = lane >> 2;
    const int cid2 = (lane & 3) * 2;
    #pragma unroll
    for (int mt = 0; mt < 2; mt++) {
        #pragma unroll
        for (int hf = 0; hf < 2; hf++) {
            int row = rowBase + warpM * 32 + mt * 16 + qid + hf * 8;
            if (SCATTER) row = map_row(row);
            #pragma unroll
            for (int n = 0; n < 4; n++) {
                int col = colBase + warpN * 32 + n * 8 + cid2;
                float2 bv = *(const float2*)(bias + col);
                float ox = acc[mt][n][hf * 2 + 0] + bv.x;
                float oy = acc[mt][n][hf * 2 + 1] + bv.y;
                if (DOGELU) {
                    ox = 0.5f * ox * (1.0f + erff(ox * 0.70710678118654752f));
                    oy = 0.5f * oy * (1.0f + erff(oy * 0.70710678118654752f));
                }
                if (Ou) {
                    *(uint2*)(Ou + (size_t)row * N + col) = make_uint2(ipack(ox), ipack(oy));
                } else {
                    *(float2*)(Of + (size_t)row * N + col) = make_float2(ox, oy);
                }
            }
        }
    }
}

// ---------------------------------------------------------------------------
// Attention: one block per (window, head), 64 threads = 64 query rows.
// qkv rows are interleaved uint32 per logical col, stride NP_QKV halves.
// ---------------------------------------------------------------------------
__global__ __launch_bounds__(64) void attn_k(
    const uint32_t* __restrict__ qkv, const float* __restrict__ rpbd,
    const float* __restrict__ mask, uint32_t* __restrict__ outp)
{
    const int blk = blockIdx.x;
    const int w   = blk / NH;
    const int hh  = blk % NH;
    const int t    = threadIdx.x;
    const int lane = t & 31;
    const int wrp  = t >> 5;

    __shared__ float Qs[64][33];
    __shared__ float Ks[64][33];
    __shared__ float Vs[64][33];

    const size_t rowbase = (size_t)w * 64;
    for (int j = wrp; j < 64; j += 2) {
        const uint32_t* p = qkv + (rowbase + j) * QKV_N + hh * 32 + lane;
        Qs[j][lane] = iunpack(p[0]);
        Ks[j][lane] = iunpack(p[192]);
        Vs[j][lane] = iunpack(p[384]);
    }
    __syncthreads();

    float q[32];
    #pragma unroll
    for (int d = 0; d < 32; d++) q[d] = Qs[t][d];

    float s[64];
    #pragma unroll
    for (int j = 0; j < 64; j++) {
        float a = 0.f;
        #pragma unroll
        for (int d = 0; d < 32; d++) a = fmaf(q[d], Ks[j][d], a);
        s[j] = a * SCALE_F;
    }

    const float* mrow = mask + ((w & 1023) * 4096 + t * 64);
    const float* rrow = rpbd + hh * 4096 + t * 64;
    float mx = -1e30f;
    #pragma unroll
    for (int j = 0; j < 64; j++) {
        s[j] += rrow[j] + mrow[j];
        mx = fmaxf(mx, s[j]);
    }
    float sum = 0.f;
    #pragma unroll
    for (int j = 0; j < 64; j++) { s[j] = expf(s[j] - mx); sum += s[j]; }
    const float inv = 1.f / sum;

    float o[32] = {};
    #pragma unroll
    for (int j = 0; j < 64; j++) {
        float p = s[j] * inv;
        #pragma unroll
        for (int d = 0; d < 32; d++) o[d] = fmaf(p, Vs[j][d], o[d]);
    }

    uint32_t* op = outp + (rowbase + t) * C_DIM + hh * 32;
    #pragma unroll
    for (int d = 0; d < 32; d += 4)
        *(uint4*)(op + d) = make_uint4(ipack(o[d]), ipack(o[d+1]), ipack(o[d+2]), ipack(o[d+3]));
}

// ---------------------------------------------------------------------------
// LN1: x1 = resx(fp32) + LN(y)*g+b ; y,x1 interleaved
// ---------------------------------------------------------------------------
__global__ __launch_bounds__(256) void ln1_k(
    const uint32_t* __restrict__ y, const float* __restrict__ resx,
    const float* __restrict__ g, const float* __restrict__ b,
    uint32_t* __restrict__ o1)
{
    const size_t token = (size_t)blockIdx.x * 8 + (threadIdx.x >> 5);
    const int lane = threadIdx.x & 31;
    const size_t yb = token * C_DIM;

    float v[6];
    float sum = 0.f;
    #pragma unroll
    for (int i = 0; i < 6; i++) { v[i] = iunpack(y[yb + lane + 32 * i]); sum += v[i]; }
    #pragma unroll
    for (int o = 16; o; o >>= 1) sum += __shfl_xor_sync(0xffffffffu, sum, o);
    const float mu = sum * (1.f / 192.f);
    float sq = 0.f;
    #pragma unroll
    for (int i = 0; i < 6; i++) { float d = v[i] - mu; sq = fmaf(d, d, sq); }
    #pragma unroll
    for (int o = 16; o; o >>= 1) sq += __shfl_xor_sync(0xffffffffu, sq, o);
    const float inv = rsqrtf(sq * (1.f / 192.f) + 1e-5f);

    #pragma unroll
    for (int i = 0; i < 6; i++) {
        int c = lane + 32 * i;
        o1[yb + c] = ipack(resx[yb + c] + (v[i] - mu) * inv * g[c] + b[c]);
    }
}

// LN2: out(fp32) = res(x1) + LN(y)*g+b
__global__ __launch_bounds__(256) void ln2_k(
    const uint32_t* __restrict__ y, const uint32_t* __restrict__ r,
    const float* __restrict__ g, const float* __restrict__ b,
    float* __restrict__ outp)
{
    const size_t token = (size_t)blockIdx.x * 8 + (threadIdx.x >> 5);
    const int lane = threadIdx.x & 31;
    const size_t yb = token * C_DIM;

    float v[6];
    float sum = 0.f;
    #pragma unroll
    for (int i = 0; i < 6; i++) { v[i] = iunpack(y[yb + lane + 32 * i]); sum += v[i]; }
    #pragma unroll
    for (int o = 16; o; o >>= 1) sum += __shfl_xor_sync(0xffffffffu, sum, o);
    const float mu = sum * (1.f / 192.f);
    float sq = 0.f;
    #pragma unroll
    for (int i = 0; i < 6; i++) { float d = v[i] - mu; sq = fmaf(d, d, sq); }
    #pragma unroll
    for (int o = 16; o; o >>= 1) sq += __shfl_xor_sync(0xffffffffu, sq, o);
    const float inv = rsqrtf(sq * (1.f / 192.f) + 1e-5f);

    #pragma unroll
    for (int i = 0; i < 6; i++) {
        int c = lane + 32 * i;
        outp[yb + c] = iunpack(r[yb + c]) + (v[i] - mu) * inv * g[c] + b[c];
    }
}

// ---------------------------------------------------------------------------
// Launch
// ---------------------------------------------------------------------------
extern "C" void kernel_launch(void* const* d_in, const int* in_sizes, int n_in,
                              void* d_out, int out_size)
{
    const float* x      = (const float*)d_in[0];
    const float* mask   = (const float*)d_in[1];
    const int*   relidx = (const int*)  d_in[2];
    const float* qkv_w  = (const float*)d_in[3];
    const float* qkv_b  = (const float*)d_in[4];
    const float* proj_w = (const float*)d_in[5];
    const float* proj_b = (const float*)d_in[6];
    const float* rpb    = (const float*)d_in[7];
    const float* n1g    = (const float*)d_in[8];
    const float* n1b    = (const float*)d_in[9];
    const float* n2g    = (const float*)d_in[10];
    const float* n2b    = (const float*)d_in[11];
    const float* fc1w   = (const float*)d_in[12];
    const float* fc1b   = (const float*)d_in[13];
    const float* fc2w   = (const float*)d_in[14];
    const float* fc2b   = (const float*)d_in[15];
    float* out = (float*)d_out;

    char* pool;
    cudaGetSymbolAddress((void**)&pool, g_pool);
    uint32_t* q  = (uint32_t*)(pool);
    uint32_t* h  = (uint32_t*)(pool);            // time-disjoint with q
    uint32_t* xb = (uint32_t*)(pool + OFF_X);
    uint32_t* a  = (uint32_t*)(pool + OFF_X);    // time-disjoint with xb
    uint32_t* tb = (uint32_t*)(pool + OFF_T);
    uint32_t* x1 = (uint32_t*)(pool + OFF_X1);

    __half *wq, *wp, *w1, *w2;
    float* rpbd;
    cudaGetSymbolAddress((void**)&wq, g_wq);
    cudaGetSymbolAddress((void**)&wp, g_wp);
    cudaGetSymbolAddress((void**)&w1, g_w1);
    cudaGetSymbolAddress((void**)&w2, g_w2);
    cudaGetSymbolAddress((void**)&rpbd, g_rpbd);

    cudaFuncSetAttribute(mm_i<false, false>, cudaFuncAttributeMaxDynamicSharedMemorySize, MMSMEM);
    cudaFuncSetAttribute(mm_i<true,  false>, cudaFuncAttributeMaxDynamicSharedMemorySize, MMSMEM);
    cudaFuncSetAttribute(mm_i<false, true >, cudaFuncAttributeMaxDynamicSharedMemorySize, MMSMEM);

    // 0. preps
    prep_w<<<(QKV_N  * (C_DIM  / 4)) / 256, 256>>>(qkv_w,  (uint32_t*)wq, C_DIM);
    prep_w<<<(C_DIM  * (C_DIM  / 4)) / 256, 256>>>(proj_w, (uint32_t*)wp, C_DIM);
    prep_w<<<(HIDDEN * (C_DIM  / 4)) / 256, 256>>>(fc1w,   (uint32_t*)w1, C_DIM);
    prep_w<<<(C_DIM  * (HIDDEN / 4)) / 256, 256>>>(fc2w,   (uint32_t*)w2, HIDDEN);
    prep_rpb<<<(NH * 4096) / 256, 256>>>(rpb, relidx, rpbd);
    prep_x<<<(M_TOT * 48) / 256, 256>>>(x, xb);

    // 1. qkv GEMM: [M,192] x [576,192]^T   (N=576 = 9 tiles of 64)
    mm_i<false, false><<<dim3(QKV_N / 64, M_TOT / BM), 256, MMSMEM>>>(
        (const __half*)xb, wq, qkv_b, q, nullptr, QKV_N, KP_CD);

    // 2. windowed attention
    attn_k<<<NWIN * NH, 64>>>(q, rpbd, mask, a);

    // 3. proj GEMM + scatter to image layout
    mm_i<true, false><<<dim3(C_DIM / 64, M_TOT / BM), 256, MMSMEM>>>(
        (const __half*)a, wp, proj_b, tb, nullptr, C_DIM, KP_CD);

    // 4. x1 = x + LN1(proj_img)
    ln1_k<<<M_TOT / 8, 256>>>(tb, x, n1g, n1b, x1);

    // 5. fc1 + GELU
    mm_i<false, true><<<dim3(HIDDEN / 64, M_TOT / BM), 256, MMSMEM>>>(
        (const __half*)x1, w1, fc1b, h, nullptr, HIDDEN, KP_CD);

    // 6. fc2
    mm_i<false, false><<<dim3(C_DIM / 64, M_TOT / BM), 256, MMSMEM>>>(
        (const __half*)h, w2, fc2b, tb, nullptr, C_DIM, KP_HI);

    // 7. out = x1 + LN2(fc2_out)
    ln2_k<<<M_TOT / 8, 256>>>(tb, x1, n2g, n2b, out);
}

// round 9
// speedup vs baseline: 1.7190x; 1.2339x over previous
#include <cuda_runtime.h>
#include <cuda_fp16.h>
#include <math.h>
#include <stdint.h>

// ---------------------------------------------------------------------------
#define C_DIM   192
#define NH      6
#define NWIN    4096
#define M_TOT   262144
#define HIDDEN  768
#define QKV_N   576
#define SCALE_F 0.17677669529663687f

// ---------------------------------------------------------------------------
// Shared scratch pool, time-disjoint offsets.
//   q (fp16, M*576)  [0)        live: qkv->attn     | h (fp16, M*768) same slot
//   x/a (fp16, M*192) OFF_XA    x: prep->qkv; a: attn->proj (disjoint)
//   t (fp32, M*192)   OFF_T     proj->ln1, fc2->ln2
//   x1f (fp32, M*192) OFF_X1F   ln1->ln2 residual
//   x1h (fp16, M*192) OFF_X1H   ln1->fc1 GEMM input
// ---------------------------------------------------------------------------
#define SZ_H16  ((size_t)M_TOT * HIDDEN * 2)     // 402,653,184 (covers q too)
#define SZ_CD16 ((size_t)M_TOT * C_DIM * 2)      // 100,663,296
#define SZ_CD32 ((size_t)M_TOT * C_DIM * 4)      // 201,326,592
#define OFF_XA  (SZ_H16)
#define OFF_T   (OFF_XA + SZ_CD16)
#define OFF_X1F (OFF_T + SZ_CD32)
#define OFF_X1H (OFF_X1F + SZ_CD32)
#define POOLSZ  (OFF_X1H + SZ_CD16)              // ~1.0 GB

__device__ __align__(256) char g_pool[POOLSZ];

__device__ __half g_wq[QKV_N * C_DIM];
__device__ __half g_wp[C_DIM * C_DIM];
__device__ __half g_w1[HIDDEN * C_DIM];
__device__ __half g_w2[C_DIM * HIDDEN];
__device__ float  g_rpbd[NH * 64 * 64];

// ---------------------------------------------------------------------------
__device__ __forceinline__ int map_row(int m) {
    int w    = m >> 6;
    int t    = m & 63;
    int b    = w >> 10;
    int widx = w & 1023;
    int wh   = widx >> 5;
    int ww   = widx & 31;
    int r    = t >> 3;
    int c    = t & 7;
    int h    = (wh * 8 + r + 4) & 255;
    int wc   = (ww * 8 + c + 4) & 255;
    return (b << 16) | (h << 8) | wc;
}

__device__ __forceinline__ uint32_t smem_to_u32(const void* p) {
    uint32_t a;
    asm("{ .reg .u64 t; cvta.to.shared.u64 t, %1; cvt.u32.u64 %0, t; }" : "=r"(a) : "l"(p));
    return a;
}

#define CP_ASYNC16(dst, src) \
    asm volatile("cp.async.cg.shared.global [%0], [%1], 16;" :: "r"(dst), "l"(src))
#define CP_COMMIT() asm volatile("cp.async.commit_group;")
#define CP_WAIT(n)  asm volatile("cp.async.wait_group %0;" :: "n"(n))

#define LDM_X4(r0, r1, r2, r3, addr) \
    asm volatile("ldmatrix.sync.aligned.m8n8.x4.shared.b16 {%0,%1,%2,%3}, [%4];" \
                 : "=r"(r0), "=r"(r1), "=r"(r2), "=r"(r3) : "r"(addr))

#define MMA_F16(d, a, b) \
    asm volatile("mma.sync.aligned.m16n8k16.row.col.f32.f16.f16.f32 " \
                 "{%0,%1,%2,%3}, {%4,%5,%6,%7}, {%8,%9}, {%0,%1,%2,%3};" \
                 : "+f"((d)[0]), "+f"((d)[1]), "+f"((d)[2]), "+f"((d)[3]) \
                 : "r"((a)[0]), "r"((a)[1]), "r"((a)[2]), "r"((a)[3]), \
                   "r"((b)[0]), "r"((b)[1]))

__device__ __forceinline__ uint32_t pk_h2(float x, float y) {
    __half2 t = __floats2half2_rn(x, y);
    return *(uint32_t*)&t;
}

// ---------------------------------------------------------------------------
// Prep kernels
// ---------------------------------------------------------------------------
__global__ __launch_bounds__(256) void prep_x(
    const float* __restrict__ x, uint32_t* __restrict__ xo)   // xo: 2 fp16/word
{
    int idx = blockIdx.x * 256 + threadIdx.x;      // M_TOT * 48
    int m = idx / 48, c4 = idx % 48;
    float4 v = *(const float4*)(x + (size_t)map_row(m) * C_DIM + c4 * 4);
    *(uint2*)(xo + ((size_t)m * C_DIM + c4 * 4) / 2) =
        make_uint2(pk_h2(v.x, v.y), pk_h2(v.z, v.w));
}

__global__ __launch_bounds__(256) void prep_w(
    const float* __restrict__ w, uint32_t* __restrict__ wo, int K)
{
    int idx = blockIdx.x * 256 + threadIdx.x;      // rows * K/4
    int k4 = K / 4;
    int row = idx / k4, c4 = idx % k4;
    float4 v = *(const float4*)(w + (size_t)row * K + c4 * 4);
    *(uint2*)(wo + ((size_t)row * K + c4 * 4) / 2) =
        make_uint2(pk_h2(v.x, v.y), pk_h2(v.z, v.w));
}

__global__ void prep_rpb(const float* __restrict__ rpb_table, const int* __restrict__ rel_idx,
                         float* __restrict__ rpbd)
{
    int idx = blockIdx.x * 256 + threadIdx.x;      // NH*4096
    int h = idx >> 12, tj = idx & 4095;
    rpbd[idx] = rpb_table[rel_idx[tj] * NH + h];
}

// ---------------------------------------------------------------------------
// Plain fp16 HMMA GEMM, cp.async 3-stage.
// C[m,n] = sum_k A[m,k] W[n,k] + bias[n].
// BM=128, BN=64, BK=64. 256 threads, warps 4(M) x 2(N), warp tile 32x32.
// Output: fp16 (Ou) or fp32 (Of).
// ---------------------------------------------------------------------------
#define BM   128
#define BK   64
#define RS   144             // smem row stride bytes (128 data + 16 pad)
#define ATB  (128 * RS)
#define BTB  (64 * RS)
#define SSTG (ATB + BTB)     // 27648
#define NSTG 3
#define MMSMEM (NSTG * SSTG) // 82944

template<bool SCATTER, bool DOGELU>
__global__ __launch_bounds__(256, 2) void mm_f16(
    const __half* __restrict__ A, const __half* __restrict__ W,
    const float* __restrict__ bias, uint32_t* __restrict__ Ou,
    float* __restrict__ Of, int N, int K)
{
    extern __shared__ char sm[];
    const uint32_t sbase = smem_to_u32(sm);

    const int tid = threadIdx.x, wid = tid >> 5, lane = tid & 31;
    const int warpM = wid & 3, warpN = wid >> 2;
    const int rowBase = blockIdx.y * BM;
    const int colBase = blockIdx.x * 64;
    const int nch = K / BK;

    // staging: A 1024 16B chunks (4/thr), B 512 (2/thr); 8 chunks per row-slice
    const __half* aSrc[4]; uint32_t aDst[4];
    #pragma unroll
    for (int t = 0; t < 4; t++) {
        int idx = tid + t * 256;
        int row = idx >> 3, kc = idx & 7;
        aSrc[t] = A + (size_t)(rowBase + row) * K + kc * 8;
        aDst[t] = row * RS + kc * 16;
    }
    const __half* bSrc[2]; uint32_t bDst[2];
    #pragma unroll
    for (int t = 0; t < 2; t++) {
        int idx = tid + t * 256;
        int row = idx >> 3, kc = idx & 7;
        bSrc[t] = W + (size_t)(colBase + row) * K + kc * 8;
        bDst[t] = ATB + row * RS + kc * 16;
    }

    auto issue = [&](int s, int it) {
        uint32_t sb = sbase + s * SSTG;
        int k0 = it * BK;
        #pragma unroll
        for (int t = 0; t < 4; t++) CP_ASYNC16(sb + aDst[t], aSrc[t] + k0);
        #pragma unroll
        for (int t = 0; t < 2; t++) CP_ASYNC16(sb + bDst[t], bSrc[t] + k0);
        CP_COMMIT();
    };

    const uint32_t aRowL = (uint32_t)(warpM * 32 + (lane & 15));
    const uint32_t aColB = (uint32_t)(((lane >> 4) * 8) * 2);
    const uint32_t bRowL = (uint32_t)(warpN * 32 + (lane & 7) + ((lane >> 4) << 3));
    const uint32_t bColB = (uint32_t)((((lane >> 3) & 1) * 8) * 2);

    float acc[2][4][4] = {};

    issue(0, 0);
    issue(1, 1);

    for (int it = 0; it < nch; it++) {
        CP_WAIT(1);
        __syncthreads();
        const uint32_t stg = sbase + (it % NSTG) * SSTG;

        #pragma unroll
        for (int kk = 0; kk < BK; kk += 16) {
            uint32_t ah[2][4], bb[2][4];
            #pragma unroll
            for (int mt = 0; mt < 2; mt++) {
                uint32_t off = (aRowL + mt * 16) * RS + aColB + kk * 2;
                LDM_X4(ah[mt][0], ah[mt][1], ah[mt][2], ah[mt][3], stg + off);
            }
            #pragma unroll
            for (int nt2 = 0; nt2 < 2; nt2++) {
                uint32_t off = ATB + (bRowL + nt2 * 16) * RS + bColB + kk * 2;
                LDM_X4(bb[nt2][0], bb[nt2][1], bb[nt2][2], bb[nt2][3], stg + off);
            }
            #pragma unroll
            for (int mt = 0; mt < 2; mt++) {
                #pragma unroll
                for (int n = 0; n < 4; n++) {
                    uint32_t bf[2] = { bb[n >> 1][(n & 1) * 2], bb[n >> 1][(n & 1) * 2 + 1] };
                    MMA_F16(acc[mt][n], ah[mt], bf);
                }
            }
        }

        int nxt = it + NSTG - 1;
        if (nxt < nch) issue(nxt % NSTG, nxt);
        else           CP_COMMIT();
    }

    // ---- epilogue ----
    const int qid = lane >> 2;
    const int cid2 = (lane & 3) * 2;
    #pragma unroll
    for (int mt = 0; mt < 2; mt++) {
        #pragma unroll
        for (int hf = 0; hf < 2; hf++) {
            int row = rowBase + warpM * 32 + mt * 16 + qid + hf * 8;
            if (SCATTER) row = map_row(row);
            #pragma unroll
            for (int n = 0; n < 4; n++) {
                int col = colBase + warpN * 32 + n * 8 + cid2;
                float2 bv = *(const float2*)(bias + col);
                float ox = acc[mt][n][hf * 2 + 0] + bv.x;
                float oy = acc[mt][n][hf * 2 + 1] + bv.y;
                if (DOGELU) {
                    ox = 0.5f * ox * (1.0f + erff(ox * 0.70710678118654752f));
                    oy = 0.5f * oy * (1.0f + erff(oy * 0.70710678118654752f));
                }
                if (Ou) *(uint32_t*)(Ou + ((size_t)row * N + col) / 2) = pk_h2(ox, oy);
                else    *(float2*)(Of + (size_t)row * N + col) = make_float2(ox, oy);
            }
        }
    }
}

// ---------------------------------------------------------------------------
// Attention: one block per (window, head), 64 threads = 64 query rows.
// ---------------------------------------------------------------------------
__global__ __launch_bounds__(64) void attn_k(
    const __half* __restrict__ qkv, const float* __restrict__ rpbd,
    const float* __restrict__ mask, uint32_t* __restrict__ outp)
{
    const int blk = blockIdx.x;
    const int w   = blk / NH;
    const int hh  = blk % NH;
    const int t    = threadIdx.x;
    const int lane = t & 31;
    const int wrp  = t >> 5;

    __shared__ float Qs[64][33];
    __shared__ float Ks[64][33];
    __shared__ float Vs[64][33];

    const size_t rowbase = (size_t)w * 64;
    for (int j = wrp; j < 64; j += 2) {
        const __half* p = qkv + (rowbase + j) * QKV_N + hh * 32 + lane;
        Qs[j][lane] = __half2float(p[0]);
        Ks[j][lane] = __half2float(p[192]);
        Vs[j][lane] = __half2float(p[384]);
    }
    __syncthreads();

    float q[32];
    #pragma unroll
    for (int d = 0; d < 32; d++) q[d] = Qs[t][d];

    float s[64];
    #pragma unroll
    for (int j = 0; j < 64; j++) {
        float a = 0.f;
        #pragma unroll
        for (int d = 0; d < 32; d++) a = fmaf(q[d], Ks[j][d], a);
        s[j] = a * SCALE_F;
    }

    const float* mrow = mask + ((w & 1023) * 4096 + t * 64);
    const float* rrow = rpbd + hh * 4096 + t * 64;
    float mx = -1e30f;
    #pragma unroll
    for (int j = 0; j < 64; j++) {
        s[j] += rrow[j] + mrow[j];
        mx = fmaxf(mx, s[j]);
    }
    float sum = 0.f;
    #pragma unroll
    for (int j = 0; j < 64; j++) { s[j] = expf(s[j] - mx); sum += s[j]; }
    const float inv = 1.f / sum;

    float o[32] = {};
    #pragma unroll
    for (int j = 0; j < 64; j++) {
        float p = s[j] * inv;
        #pragma unroll
        for (int d = 0; d < 32; d++) o[d] = fmaf(p, Vs[j][d], o[d]);
    }

    uint32_t* op = outp + ((rowbase + t) * C_DIM + hh * 32) / 2;
    #pragma unroll
    for (int d = 0; d < 32; d += 8)
        *(uint4*)(op + d / 2) = make_uint4(pk_h2(o[d], o[d+1]), pk_h2(o[d+2], o[d+3]),
                                           pk_h2(o[d+4], o[d+5]), pk_h2(o[d+6], o[d+7]));
}

// ---------------------------------------------------------------------------
// LN1: x1 = resx(fp32) + LN(y fp32)*g+b ; writes fp32 (residual) + fp16 (GEMM in)
// ---------------------------------------------------------------------------
__global__ __launch_bounds__(256) void ln1_k(
    const float* __restrict__ y, const float* __restrict__ resx,
    const float* __restrict__ g, const float* __restrict__ b,
    float* __restrict__ of, uint32_t* __restrict__ oh)
{
    const size_t token = (size_t)blockIdx.x * 8 + (threadIdx.x >> 5);
    const int lane = threadIdx.x & 31;
    const size_t yb = token * C_DIM;

    float v[6];
    float sum = 0.f;
    #pragma unroll
    for (int i = 0; i < 6; i++) { v[i] = y[yb + lane + 32 * i]; sum += v[i]; }
    #pragma unroll
    for (int o = 16; o; o >>= 1) sum += __shfl_xor_sync(0xffffffffu, sum, o);
    const float mu = sum * (1.f / 192.f);
    float sq = 0.f;
    #pragma unroll
    for (int i = 0; i < 6; i++) { float d = v[i] - mu; sq = fmaf(d, d, sq); }
    #pragma unroll
    for (int o = 16; o; o >>= 1) sq += __shfl_xor_sync(0xffffffffu, sq, o);
    const float inv = rsqrtf(sq * (1.f / 192.f) + 1e-5f);

    float r[6];
    #pragma unroll
    for (int i = 0; i < 6; i++) {
        int c = lane + 32 * i;
        r[i] = resx[yb + c] + (v[i] - mu) * inv * g[c] + b[c];
        of[yb + c] = r[i];
    }
    // fp16 copy: pack pairs along c within this lane's strided set is not
    // contiguous; write via half stores (L1 write-combines fine).
    #pragma unroll
    for (int i = 0; i < 6; i++) {
        int c = lane + 32 * i;
        ((__half*)oh)[yb + c] = __float2half_rn(r[i]);
    }
}

// LN2: out(fp32) = res(x1 fp32) + LN(y fp32)*g+b
__global__ __launch_bounds__(256) void ln2_k(
    const float* __restrict__ y, const float* __restrict__ r,
    const float* __restrict__ g, const float* __restrict__ b,
    float* __restrict__ outp)
{
    const size_t token = (size_t)blockIdx.x * 8 + (threadIdx.x >> 5);
    const int lane = threadIdx.x & 31;
    const size_t yb = token * C_DIM;

    float v[6];
    float sum = 0.f;
    #pragma unroll
    for (int i = 0; i < 6; i++) { v[i] = y[yb + lane + 32 * i]; sum += v[i]; }
    #pragma unroll
    for (int o = 16; o; o >>= 1) sum += __shfl_xor_sync(0xffffffffu, sum, o);
    const float mu = sum * (1.f / 192.f);
    float sq = 0.f;
    #pragma unroll
    for (int i = 0; i < 6; i++) { float d = v[i] - mu; sq = fmaf(d, d, sq); }
    #pragma unroll
    for (int o = 16; o; o >>= 1) sq += __shfl_xor_sync(0xffffffffu, sq, o);
    const float inv = rsqrtf(sq * (1.f / 192.f) + 1e-5f);

    #pragma unroll
    for (int i = 0; i < 6; i++) {
        int c = lane + 32 * i;
        outp[yb + c] = r[yb + c] + (v[i] - mu) * inv * g[c] + b[c];
    }
}

// ---------------------------------------------------------------------------
// Launch
// ---------------------------------------------------------------------------
extern "C" void kernel_launch(void* const* d_in, const int* in_sizes, int n_in,
                              void* d_out, int out_size)
{
    const float* x      = (const float*)d_in[0];
    const float* mask   = (const float*)d_in[1];
    const int*   relidx = (const int*)  d_in[2];
    const float* qkv_w  = (const float*)d_in[3];
    const float* qkv_b  = (const float*)d_in[4];
    const float* proj_w = (const float*)d_in[5];
    const float* proj_b = (const float*)d_in[6];
    const float* rpb    = (const float*)d_in[7];
    const float* n1g    = (const float*)d_in[8];
    const float* n1b    = (const float*)d_in[9];
    const float* n2g    = (const float*)d_in[10];
    const float* n2b    = (const float*)d_in[11];
    const float* fc1w   = (const float*)d_in[12];
    const float* fc1b   = (const float*)d_in[13];
    const float* fc2w   = (const float*)d_in[14];
    const float* fc2b   = (const float*)d_in[15];
    float* out = (float*)d_out;

    char* pool;
    cudaGetSymbolAddress((void**)&pool, g_pool);
    __half*   q   = (__half*)(pool);                 // fp16 M x 576
    __half*   h   = (__half*)(pool);                 // fp16 M x 768 (disjoint)
    __half*   xb  = (__half*)(pool + OFF_XA);        // fp16 M x 192
    __half*   a   = (__half*)(pool + OFF_XA);        // (disjoint with xb)
    float*    tb  = (float*)(pool + OFF_T);          // fp32 M x 192
    float*    x1f = (float*)(pool + OFF_X1F);        // fp32 M x 192
    uint32_t* x1h = (uint32_t*)(pool + OFF_X1H);     // fp16 M x 192

    __half *wq, *wp, *w1, *w2;
    float* rpbd;
    cudaGetSymbolAddress((void**)&wq, g_wq);
    cudaGetSymbolAddress((void**)&wp, g_wp);
    cudaGetSymbolAddress((void**)&w1, g_w1);
    cudaGetSymbolAddress((void**)&w2, g_w2);
    cudaGetSymbolAddress((void**)&rpbd, g_rpbd);

    cudaFuncSetAttribute(mm_f16<false, false>, cudaFuncAttributeMaxDynamicSharedMemorySize, MMSMEM);
    cudaFuncSetAttribute(mm_f16<true,  false>, cudaFuncAttributeMaxDynamicSharedMemorySize, MMSMEM);
    cudaFuncSetAttribute(mm_f16<false, true >, cudaFuncAttributeMaxDynamicSharedMemorySize, MMSMEM);

    // 0. preps
    prep_w<<<(QKV_N  * (C_DIM  / 4)) / 256, 256>>>(qkv_w,  (uint32_t*)wq, C_DIM);
    prep_w<<<(C_DIM  * (C_DIM  / 4)) / 256, 256>>>(proj_w, (uint32_t*)wp, C_DIM);
    prep_w<<<(HIDDEN * (C_DIM  / 4)) / 256, 256>>>(fc1w,   (uint32_t*)w1, C_DIM);
    prep_w<<<(C_DIM  * (HIDDEN / 4)) / 256, 256>>>(fc2w,   (uint32_t*)w2, HIDDEN);
    prep_rpb<<<(NH * 4096) / 256, 256>>>(rpb, relidx, rpbd);
    prep_x<<<(M_TOT * 48) / 256, 256>>>(x, (uint32_t*)xb);

    // 1. qkv GEMM: [M,192] x [576,192]^T, fp16 out
    mm_f16<false, false><<<dim3(QKV_N / 64, M_TOT / BM), 256, MMSMEM>>>(
        xb, wq, qkv_b, (uint32_t*)q, nullptr, QKV_N, C_DIM);

    // 2. windowed attention, fp16 out
    attn_k<<<NWIN * NH, 64>>>(q, rpbd, mask, (uint32_t*)a);

    // 3. proj GEMM + scatter, fp32 out
    mm_f16<true, false><<<dim3(C_DIM / 64, M_TOT / BM), 256, MMSMEM>>>(
        a, wp, proj_b, nullptr, tb, C_DIM, C_DIM);

    // 4. x1 = x + LN1(proj_img): fp32 + fp16 copies
    ln1_k<<<M_TOT / 8, 256>>>(tb, x, n1g, n1b, x1f, x1h);

    // 5. fc1 + GELU, fp16 out
    mm_f16<false, true><<<dim3(HIDDEN / 64, M_TOT / BM), 256, MMSMEM>>>(
        (const __half*)x1h, w1, fc1b, (uint32_t*)h, nullptr, HIDDEN, C_DIM);

    // 6. fc2, fp32 out
    mm_f16<false, false><<<dim3(C_DIM / 64, M_TOT / BM), 256, MMSMEM>>>(
        h, w2, fc2b, nullptr, tb, C_DIM, HIDDEN);

    // 7. out = x1 + LN2(fc2_out)
    ln2_k<<<M_TOT / 8, 256>>>(tb, x1f, n2g, n2b, out);
}

// round 11
// speedup vs baseline: 2.8765x; 1.6734x over previous
#include <cuda_runtime.h>
#include <cuda_fp16.h>
#include <math.h>
#include <stdint.h>

// ---------------------------------------------------------------------------
#define C_DIM   192
#define NH      6
#define NWIN    4096
#define M_TOT   262144
#define HIDDEN  768
#define QKV_N   576
#define SCALE_F 0.17677669529663687f

// ---------------------------------------------------------------------------
// Shared scratch pool, time-disjoint offsets (same as R9).
// ---------------------------------------------------------------------------
#define SZ_H16  ((size_t)M_TOT * HIDDEN * 2)
#define SZ_CD16 ((size_t)M_TOT * C_DIM * 2)
#define SZ_CD32 ((size_t)M_TOT * C_DIM * 4)
#define OFF_XA  (SZ_H16)
#define OFF_T   (OFF_XA + SZ_CD16)
#define OFF_X1F (OFF_T + SZ_CD32)
#define OFF_X1H (OFF_X1F + SZ_CD32)
#define POOLSZ  (OFF_X1H + SZ_CD16)

__device__ __align__(256) char g_pool[POOLSZ];

__device__ __half g_wq[QKV_N * C_DIM];
__device__ __half g_wp[C_DIM * C_DIM];
__device__ __half g_w1[HIDDEN * C_DIM];
__device__ __half g_w2[C_DIM * HIDDEN];
__device__ float  g_rpbd[NH * 64 * 64];

// ---------------------------------------------------------------------------
__device__ __forceinline__ int map_row(int m) {
    int w    = m >> 6;
    int t    = m & 63;
    int b    = w >> 10;
    int widx = w & 1023;
    int wh   = widx >> 5;
    int ww   = widx & 31;
    int r    = t >> 3;
    int c    = t & 7;
    int h    = (wh * 8 + r + 4) & 255;
    int wc   = (ww * 8 + c + 4) & 255;
    return (b << 16) | (h << 8) | wc;
}

__device__ __forceinline__ uint32_t smem_to_u32(const void* p) {
    uint32_t a;
    asm("{ .reg .u64 t; cvta.to.shared.u64 t, %1; cvt.u32.u64 %0, t; }" : "=r"(a) : "l"(p));
    return a;
}

#define CP_ASYNC16(dst, src) \
    asm volatile("cp.async.cg.shared.global [%0], [%1], 16;" :: "r"(dst), "l"(src))
#define CP_COMMIT() asm volatile("cp.async.commit_group;")
#define CP_WAIT(n)  asm volatile("cp.async.wait_group %0;" :: "n"(n))

#define LDM_X4(r0, r1, r2, r3, addr) \
    asm volatile("ldmatrix.sync.aligned.m8n8.x4.shared.b16 {%0,%1,%2,%3}, [%4];" \
                 : "=r"(r0), "=r"(r1), "=r"(r2), "=r"(r3) : "r"(addr))
#define LDM_X4_T(r0, r1, r2, r3, addr) \
    asm volatile("ldmatrix.sync.aligned.m8n8.x4.trans.shared.b16 {%0,%1,%2,%3}, [%4];" \
                 : "=r"(r0), "=r"(r1), "=r"(r2), "=r"(r3) : "r"(addr))

#define MMA_F16(d, a, b) \
    asm volatile("mma.sync.aligned.m16n8k16.row.col.f32.f16.f16.f32 " \
                 "{%0,%1,%2,%3}, {%4,%5,%6,%7}, {%8,%9}, {%0,%1,%2,%3};" \
                 : "+f"((d)[0]), "+f"((d)[1]), "+f"((d)[2]), "+f"((d)[3]) \
                 : "r"((a)[0]), "r"((a)[1]), "r"((a)[2]), "r"((a)[3]), \
                   "r"((b)[0]), "r"((b)[1]))

__device__ __forceinline__ uint32_t pk_h2(float x, float y) {
    __half2 t = __floats2half2_rn(x, y);
    return *(uint32_t*)&t;
}

// ---------------------------------------------------------------------------
// Prep kernels
// ---------------------------------------------------------------------------
__global__ __launch_bounds__(256) void prep_x(
    const float* __restrict__ x, uint32_t* __restrict__ xo)
{
    int idx = blockIdx.x * 256 + threadIdx.x;      // M_TOT * 48
    int m = idx / 48, c4 = idx % 48;
    float4 v = *(const float4*)(x + (size_t)map_row(m) * C_DIM + c4 * 4);
    *(uint2*)(xo + ((size_t)m * C_DIM + c4 * 4) / 2) =
        make_uint2(pk_h2(v.x, v.y), pk_h2(v.z, v.w));
}

__global__ __launch_bounds__(256) void prep_w(
    const float* __restrict__ w, uint32_t* __restrict__ wo, int K)
{
    int idx = blockIdx.x * 256 + threadIdx.x;      // rows * K/4
    int k4 = K / 4;
    int row = idx / k4, c4 = idx % k4;
    float4 v = *(const float4*)(w + (size_t)row * K + c4 * 4);
    *(uint2*)(wo + ((size_t)row * K + c4 * 4) / 2) =
        make_uint2(pk_h2(v.x, v.y), pk_h2(v.z, v.w));
}

__global__ void prep_rpb(const float* __restrict__ rpb_table, const int* __restrict__ rel_idx,
                         float* __restrict__ rpbd)
{
    int idx = blockIdx.x * 256 + threadIdx.x;      // NH*4096
    int h = idx >> 12, tj = idx & 4095;
    rpbd[idx] = rpb_table[rel_idx[tj] * NH + h];
}

// ---------------------------------------------------------------------------
// Plain fp16 HMMA GEMM, cp.async 3-stage (unchanged from R9).
// ---------------------------------------------------------------------------
#define BM   128
#define BK   64
#define RS   144
#define ATB  (128 * RS)
#define BTB  (64 * RS)
#define SSTG (ATB + BTB)
#define NSTG 3
#define MMSMEM (NSTG * SSTG)

template<bool SCATTER, bool DOGELU>
__global__ __launch_bounds__(256, 2) void mm_f16(
    const __half* __restrict__ A, const __half* __restrict__ W,
    const float* __restrict__ bias, uint32_t* __restrict__ Ou,
    float* __restrict__ Of, int N, int K)
{
    extern __shared__ char sm[];
    const uint32_t sbase = smem_to_u32(sm);

    const int tid = threadIdx.x, wid = tid >> 5, lane = tid & 31;
    const int warpM = wid & 3, warpN = wid >> 2;
    const int rowBase = blockIdx.y * BM;
    const int colBase = blockIdx.x * 64;
    const int nch = K / BK;

    const __half* aSrc[4]; uint32_t aDst[4];
    #pragma unroll
    for (int t = 0; t < 4; t++) {
        int idx = tid + t * 256;
        int row = idx >> 3, kc = idx & 7;
        aSrc[t] = A + (size_t)(rowBase + row) * K + kc * 8;
        aDst[t] = row * RS + kc * 16;
    }
    const __half* bSrc[2]; uint32_t bDst[2];
    #pragma unroll
    for (int t = 0; t < 2; t++) {
        int idx = tid + t * 256;
        int row = idx >> 3, kc = idx & 7;
        bSrc[t] = W + (size_t)(colBase + row) * K + kc * 8;
        bDst[t] = ATB + row * RS + kc * 16;
    }

    auto issue = [&](int s, int it) {
        uint32_t sb = sbase + s * SSTG;
        int k0 = it * BK;
        #pragma unroll
        for (int t = 0; t < 4; t++) CP_ASYNC16(sb + aDst[t], aSrc[t] + k0);
        #pragma unroll
        for (int t = 0; t < 2; t++) CP_ASYNC16(sb + bDst[t], bSrc[t] + k0);
        CP_COMMIT();
    };

    const uint32_t aRowL = (uint32_t)(warpM * 32 + (lane & 15));
    const uint32_t aColB = (uint32_t)(((lane >> 4) * 8) * 2);
    const uint32_t bRowL = (uint32_t)(warpN * 32 + (lane & 7) + ((lane >> 4) << 3));
    const uint32_t bColB = (uint32_t)((((lane >> 3) & 1) * 8) * 2);

    float acc[2][4][4] = {};

    issue(0, 0);
    issue(1, 1);

    for (int it = 0; it < nch; it++) {
        CP_WAIT(1);
        __syncthreads();
        const uint32_t stg = sbase + (it % NSTG) * SSTG;

        #pragma unroll
        for (int kk = 0; kk < BK; kk += 16) {
            uint32_t ah[2][4], bb[2][4];
            #pragma unroll
            for (int mt = 0; mt < 2; mt++) {
                uint32_t off = (aRowL + mt * 16) * RS + aColB + kk * 2;
                LDM_X4(ah[mt][0], ah[mt][1], ah[mt][2], ah[mt][3], stg + off);
            }
            #pragma unroll
            for (int nt2 = 0; nt2 < 2; nt2++) {
                uint32_t off = ATB + (bRowL + nt2 * 16) * RS + bColB + kk * 2;
                LDM_X4(bb[nt2][0], bb[nt2][1], bb[nt2][2], bb[nt2][3], stg + off);
            }
            #pragma unroll
            for (int mt = 0; mt < 2; mt++) {
                #pragma unroll
                for (int n = 0; n < 4; n++) {
                    uint32_t bf[2] = { bb[n >> 1][(n & 1) * 2], bb[n >> 1][(n & 1) * 2 + 1] };
                    MMA_F16(acc[mt][n], ah[mt], bf);
                }
            }
        }

        int nxt = it + NSTG - 1;
        if (nxt < nch) issue(nxt % NSTG, nxt);
        else           CP_COMMIT();
    }

    const int qid = lane >> 2;
    const int cid2 = (lane & 3) * 2;
    #pragma unroll
    for (int mt = 0; mt < 2; mt++) {
        #pragma unroll
        for (int hf = 0; hf < 2; hf++) {
            int row = rowBase + warpM * 32 + mt * 16 + qid + hf * 8;
            if (SCATTER) row = map_row(row);
            #pragma unroll
            for (int n = 0; n < 4; n++) {
                int col = colBase + warpN * 32 + n * 8 + cid2;
                float2 bv = *(const float2*)(bias + col);
                float ox = acc[mt][n][hf * 2 + 0] + bv.x;
                float oy = acc[mt][n][hf * 2 + 1] + bv.y;
                if (DOGELU) {
                    ox = 0.5f * ox * (1.0f + erff(ox * 0.70710678118654752f));
                    oy = 0.5f * oy * (1.0f + erff(oy * 0.70710678118654752f));
                }
                if (Ou) *(uint32_t*)(Ou + ((size_t)row * N + col) / 2) = pk_h2(ox, oy);
                else    *(float2*)(Of + (size_t)row * N + col) = make_float2(ox, oy);
            }
        }
    }
}

// ---------------------------------------------------------------------------
// Tensor-core attention. Block = 256 thr = 4 (window,head) units; each unit
// = 2 warps, one per 32 query rows. QK^T and PV via mma.sync; softmax in
// C-fragment registers.
// ---------------------------------------------------------------------------
#define AT_SMEM 61440

__global__ __launch_bounds__(256, 2) void attn_mma(
    const __half* __restrict__ qkv, const float* __restrict__ rpbd,
    const float* __restrict__ mask, uint32_t* __restrict__ outp)
{
    extern __shared__ char smraw[];
    const uint32_t sbase = smem_to_u32(smraw);
    const int tid = threadIdx.x, wid = tid >> 5, lane = tid & 31;
    const int u = wid >> 1, mhalf = wid & 1;
    const int wh = blockIdx.x * 4 + u;
    const int w = wh / NH;
    const int hh = wh - w * NH;
    const size_t rowbase = (size_t)w * 64;

    const uint32_t Qs = sbase + u * 15360;
    const uint32_t Ks = Qs + 5120;
    const uint32_t Vs = Qs + 10240;

    // ---- load Q,K,V tiles (64 x 32 half each) via cp.async ----
    {
        int t64 = mhalf * 32 + lane;
        int r0  = t64 >> 2;
        int seg = t64 & 3;
        const __half* base = qkv + rowbase * QKV_N + hh * 32 + seg * 8;
        #pragma unroll
        for (int it = 0; it < 4; it++) {
            int row = it * 16 + r0;
            const __half* src = base + (size_t)row * QKV_N;
            uint32_t d = row * 80 + seg * 16;
            CP_ASYNC16(Qs + d, src);
            CP_ASYNC16(Ks + d, src + 192);
            CP_ASYNC16(Vs + d, src + 384);
        }
        CP_COMMIT();
    }
    CP_WAIT(0);
    __syncthreads();

    const int qid = lane >> 2, cid = lane & 3;
    const int mbase = mhalf * 32;

    // ---- QK^T: s[mt][n][4], mt = 16-row tile (2), n = 8-col tile (8) ----
    const uint32_t aRow  = (uint32_t)(mbase + (lane & 15));
    const uint32_t aColB = (uint32_t)((lane >> 4) * 16);
    const uint32_t bRow  = (uint32_t)((lane & 7) + ((lane >> 4) << 3));
    const uint32_t bColB = (uint32_t)(((lane >> 3) & 1) * 16);

    float s[2][8][4] = {};
    #pragma unroll
    for (int ks = 0; ks < 2; ks++) {
        uint32_t qf[2][4];
        #pragma unroll
        for (int mt = 0; mt < 2; mt++)
            LDM_X4(qf[mt][0], qf[mt][1], qf[mt][2], qf[mt][3],
                   Qs + (aRow + mt * 16) * 80 + aColB + ks * 32);
        #pragma unroll
        for (int p = 0; p < 4; p++) {
            uint32_t kb[4];
            LDM_X4(kb[0], kb[1], kb[2], kb[3],
                   Ks + (bRow + p * 16) * 80 + bColB + ks * 32);
            #pragma unroll
            for (int mt = 0; mt < 2; mt++) {
                #pragma unroll
                for (int nn = 0; nn < 2; nn++) {
                    uint32_t bf[2] = { kb[nn * 2], kb[nn * 2 + 1] };
                    MMA_F16(s[mt][p * 2 + nn], qf[mt], bf);
                }
            }
        }
    }

    // ---- bias + softmax in fragments; pack probs to fp16 A-frags ----
    const float* mrow = mask + (size_t)(w & 1023) * 4096;
    const float* rrow = rpbd + hh * 4096;
    uint32_t pf[2][4][4];
    float inva[2], invb[2];
    #pragma unroll
    for (int mt = 0; mt < 2; mt++) {
        int t0 = mbase + mt * 16 + qid;
        int t1 = t0 + 8;
        float mx0 = -1e30f, mx1 = -1e30f;
        #pragma unroll
        for (int n = 0; n < 8; n++) {
            int j = n * 8 + cid * 2;
            float2 r0 = *(const float2*)(rrow + t0 * 64 + j);
            float2 r1 = *(const float2*)(rrow + t1 * 64 + j);
            float2 m0 = *(const float2*)(mrow + t0 * 64 + j);
            float2 m1 = *(const float2*)(mrow + t1 * 64 + j);
            s[mt][n][0] = fmaf(s[mt][n][0], SCALE_F, r0.x + m0.x);
            s[mt][n][1] = fmaf(s[mt][n][1], SCALE_F, r0.y + m0.y);
            s[mt][n][2] = fmaf(s[mt][n][2], SCALE_F, r1.x + m1.x);
            s[mt][n][3] = fmaf(s[mt][n][3], SCALE_F, r1.y + m1.y);
            mx0 = fmaxf(mx0, fmaxf(s[mt][n][0], s[mt][n][1]));
            mx1 = fmaxf(mx1, fmaxf(s[mt][n][2], s[mt][n][3]));
        }
        mx0 = fmaxf(mx0, __shfl_xor_sync(0xffffffffu, mx0, 1));
        mx0 = fmaxf(mx0, __shfl_xor_sync(0xffffffffu, mx0, 2));
        mx1 = fmaxf(mx1, __shfl_xor_sync(0xffffffffu, mx1, 1));
        mx1 = fmaxf(mx1, __shfl_xor_sync(0xffffffffu, mx1, 2));

        float sm0 = 0.f, sm1 = 0.f;
        #pragma unroll
        for (int n = 0; n < 8; n++) {
            s[mt][n][0] = expf(s[mt][n][0] - mx0);
            s[mt][n][1] = expf(s[mt][n][1] - mx0);
            s[mt][n][2] = expf(s[mt][n][2] - mx1);
            s[mt][n][3] = expf(s[mt][n][3] - mx1);
            sm0 += s[mt][n][0] + s[mt][n][1];
            sm1 += s[mt][n][2] + s[mt][n][3];
        }
        sm0 += __shfl_xor_sync(0xffffffffu, sm0, 1);
        sm0 += __shfl_xor_sync(0xffffffffu, sm0, 2);
        sm1 += __shfl_xor_sync(0xffffffffu, sm1, 1);
        sm1 += __shfl_xor_sync(0xffffffffu, sm1, 2);
        inva[mt] = 1.f / sm0;
        invb[mt] = 1.f / sm1;

        #pragma unroll
        for (int k2 = 0; k2 < 4; k2++) {
            pf[mt][k2][0] = pk_h2(s[mt][2 * k2][0],     s[mt][2 * k2][1]);
            pf[mt][k2][1] = pk_h2(s[mt][2 * k2][2],     s[mt][2 * k2][3]);
            pf[mt][k2][2] = pk_h2(s[mt][2 * k2 + 1][0], s[mt][2 * k2 + 1][1]);
            pf[mt][k2][3] = pk_h2(s[mt][2 * k2 + 1][2], s[mt][2 * k2 + 1][3]);
        }
    }

    // ---- PV: o[mt][nt][4], V via ldmatrix.trans ----
    float o[2][4][4] = {};
    const uint32_t vRow  = (uint32_t)(lane & 15);
    const uint32_t vColB = (uint32_t)((lane >> 4) * 16);
    #pragma unroll
    for (int k2 = 0; k2 < 4; k2++) {
        #pragma unroll
        for (int p = 0; p < 2; p++) {
            uint32_t vb[4];
            LDM_X4_T(vb[0], vb[1], vb[2], vb[3],
                     Vs + (k2 * 16 + vRow) * 80 + vColB + p * 32);
            #pragma unroll
            for (int mt = 0; mt < 2; mt++) {
                #pragma unroll
                for (int nn = 0; nn < 2; nn++) {
                    uint32_t bf[2] = { vb[nn * 2], vb[nn * 2 + 1] };
                    MMA_F16(o[mt][p * 2 + nn], pf[mt][k2], bf);
                }
            }
        }
    }

    // ---- normalize + store fp16 pairs ----
    #pragma unroll
    for (int mt = 0; mt < 2; mt++) {
        int t0 = mbase + mt * 16 + qid;
        int t1 = t0 + 8;
        uint32_t* o0 = outp + ((rowbase + t0) * C_DIM + hh * 32) / 2;
        uint32_t* o1 = outp + ((rowbase + t1) * C_DIM + hh * 32) / 2;
        #pragma unroll
        for (int nt = 0; nt < 4; nt++) {
            int c2 = (nt * 8 + cid * 2) >> 1;
            o0[c2] = pk_h2(o[mt][nt][0] * inva[mt], o[mt][nt][1] * inva[mt]);
            o1[c2] = pk_h2(o[mt][nt][2] * invb[mt], o[mt][nt][3] * invb[mt]);
        }
    }
}

// ---------------------------------------------------------------------------
// LN kernels (unchanged from R9)
// ---------------------------------------------------------------------------
__global__ __launch_bounds__(256) void ln1_k(
    const float* __restrict__ y, const float* __restrict__ resx,
    const float* __restrict__ g, const float* __restrict__ b,
    float* __restrict__ of, uint32_t* __restrict__ oh)
{
    const size_t token = (size_t)blockIdx.x * 8 + (threadIdx.x >> 5);
    const int lane = threadIdx.x & 31;
    const size_t yb = token * C_DIM;

    float v[6];
    float sum = 0.f;
    #pragma unroll
    for (int i = 0; i < 6; i++) { v[i] = y[yb + lane + 32 * i]; sum += v[i]; }
    #pragma unroll
    for (int o = 16; o; o >>= 1) sum += __shfl_xor_sync(0xffffffffu, sum, o);
    const float mu = sum * (1.f / 192.f);
    float sq = 0.f;
    #pragma unroll
    for (int i = 0; i < 6; i++) { float d = v[i] - mu; sq = fmaf(d, d, sq); }
    #pragma unroll
    for (int o = 16; o; o >>= 1) sq += __shfl_xor_sync(0xffffffffu, sq, o);
    const float inv = rsqrtf(sq * (1.f / 192.f) + 1e-5f);

    #pragma unroll
    for (int i = 0; i < 6; i++) {
        int c = lane + 32 * i;
        float r = resx[yb + c] + (v[i] - mu) * inv * g[c] + b[c];
        of[yb + c] = r;
        ((__half*)oh)[yb + c] = __float2half_rn(r);
    }
}

__global__ __launch_bounds__(256) void ln2_k(
    const float* __restrict__ y, const float* __restrict__ r,
    const float* __restrict__ g, const float* __restrict__ b,
    float* __restrict__ outp)
{
    const size_t token = (size_t)blockIdx.x * 8 + (threadIdx.x >> 5);
    const int lane = threadIdx.x & 31;
    const size_t yb = token * C_DIM;

    float v[6];
    float sum = 0.f;
    #pragma unroll
    for (int i = 0; i < 6; i++) { v[i] = y[yb + lane + 32 * i]; sum += v[i]; }
    #pragma unroll
    for (int o = 16; o; o >>= 1) sum += __shfl_xor_sync(0xffffffffu, sum, o);
    const float mu = sum * (1.f / 192.f);
    float sq = 0.f;
    #pragma unroll
    for (int i = 0; i < 6; i++) { float d = v[i] - mu; sq = fmaf(d, d, sq); }
    #pragma unroll
    for (int o = 16; o; o >>= 1) sq += __shfl_xor_sync(0xffffffffu, sq, o);
    const float inv = rsqrtf(sq * (1.f / 192.f) + 1e-5f);

    #pragma unroll
    for (int i = 0; i < 6; i++) {
        int c = lane + 32 * i;
        outp[yb + c] = r[yb + c] + (v[i] - mu) * inv * g[c] + b[c];
    }
}

// ---------------------------------------------------------------------------
// Launch (qkv GEMM at capture slot 4)
// ---------------------------------------------------------------------------
extern "C" void kernel_launch(void* const* d_in, const int* in_sizes, int n_in,
                              void* d_out, int out_size)
{
    const float* x      = (const float*)d_in[0];
    const float* mask   = (const float*)d_in[1];
    const int*   relidx = (const int*)  d_in[2];
    const float* qkv_w  = (const float*)d_in[3];
    const float* qkv_b  = (const float*)d_in[4];
    const float* proj_w = (const float*)d_in[5];
    const float* proj_b = (const float*)d_in[6];
    const float* rpb    = (const float*)d_in[7];
    const float* n1g    = (const float*)d_in[8];
    const float* n1b    = (const float*)d_in[9];
    const float* n2g    = (const float*)d_in[10];
    const float* n2b    = (const float*)d_in[11];
    const float* fc1w   = (const float*)d_in[12];
    const float* fc1b   = (const float*)d_in[13];
    const float* fc2w   = (const float*)d_in[14];
    const float* fc2b   = (const float*)d_in[15];
    float* out = (float*)d_out;

    char* pool;
    cudaGetSymbolAddress((void**)&pool, g_pool);
    __half*   q   = (__half*)(pool);
    __half*   h   = (__half*)(pool);
    __half*   xb  = (__half*)(pool + OFF_XA);
    __half*   a   = (__half*)(pool + OFF_XA);
    float*    tb  = (float*)(pool + OFF_T);
    float*    x1f = (float*)(pool + OFF_X1F);
    uint32_t* x1h = (uint32_t*)(pool + OFF_X1H);

    __half *wq, *wp, *w1, *w2;
    float* rpbd;
    cudaGetSymbolAddress((void**)&wq, g_wq);
    cudaGetSymbolAddress((void**)&wp, g_wp);
    cudaGetSymbolAddress((void**)&w1, g_w1);
    cudaGetSymbolAddress((void**)&w2, g_w2);
    cudaGetSymbolAddress((void**)&rpbd, g_rpbd);

    cudaFuncSetAttribute(mm_f16<false, false>, cudaFuncAttributeMaxDynamicSharedMemorySize, MMSMEM);
    cudaFuncSetAttribute(mm_f16<true,  false>, cudaFuncAttributeMaxDynamicSharedMemorySize, MMSMEM);
    cudaFuncSetAttribute(mm_f16<false, true >, cudaFuncAttributeMaxDynamicSharedMemorySize, MMSMEM);
    cudaFuncSetAttribute(attn_mma, cudaFuncAttributeMaxDynamicSharedMemorySize, AT_SMEM);

    // 1. x -> window-ordered fp16
    prep_x<<<(M_TOT * 48) / 256, 256>>>(x, (uint32_t*)xb);
    // 2. dense rpb
    prep_rpb<<<(NH * 4096) / 256, 256>>>(rpb, relidx, rpbd);
    // 3. qkv weights
    prep_w<<<(QKV_N * (C_DIM / 4)) / 256, 256>>>(qkv_w, (uint32_t*)wq, C_DIM);
    // 4. qkv GEMM  (capture slot)
    mm_f16<false, false><<<dim3(QKV_N / 64, M_TOT / BM), 256, MMSMEM>>>(
        xb, wq, qkv_b, (uint32_t*)q, nullptr, QKV_N, C_DIM);
    // 5. attention (tensor cores)
    attn_mma<<<NWIN * NH / 4, 256, AT_SMEM>>>(q, rpbd, mask, (uint32_t*)a);
    // 6. proj weights
    prep_w<<<(C_DIM * (C_DIM / 4)) / 256, 256>>>(proj_w, (uint32_t*)wp, C_DIM);
    // 7. proj GEMM + scatter, fp32 out
    mm_f16<true, false><<<dim3(C_DIM / 64, M_TOT / BM), 256, MMSMEM>>>(
        a, wp, proj_b, nullptr, tb, C_DIM, C_DIM);
    // 8. LN1
    ln1_k<<<M_TOT / 8, 256>>>(tb, x, n1g, n1b, x1f, x1h);
    // 9. fc1 weights
    prep_w<<<(HIDDEN * (C_DIM / 4)) / 256, 256>>>(fc1w, (uint32_t*)w1, C_DIM);
    // 10. fc1 + GELU
    mm_f16<false, true><<<dim3(HIDDEN / 64, M_TOT / BM), 256, MMSMEM>>>(
        (const __half*)x1h, w1, fc1b, (uint32_t*)h, nullptr, HIDDEN, C_DIM);
    // 11. fc2 weights
    prep_w<<<(C_DIM * (HIDDEN / 4)) / 256, 256>>>(fc2w, (uint32_t*)w2, HIDDEN);
    // 12. fc2
    mm_f16<false, false><<<dim3(C_DIM / 64, M_TOT / BM), 256, MMSMEM>>>(
        h, w2, fc2b, nullptr, tb, C_DIM, HIDDEN);
    // 13. LN2 -> out
    ln2_k<<<M_TOT / 8, 256>>>(tb, x1f, n2g, n2b, out);
}

// round 13
// speedup vs baseline: 3.2929x; 1.1448x over previous
#include <cuda_runtime.h>
#include <cuda_fp16.h>
#include <math.h>
#include <stdint.h>

// ---------------------------------------------------------------------------
#define C_DIM   192
#define NH      6
#define NWIN    4096
#define M_TOT   262144
#define HIDDEN  768
#define QKV_N   576
#define SCALE_F 0.17677669529663687f

// ---------------------------------------------------------------------------
// Shared scratch pool, time-disjoint offsets (same as R9).
// ---------------------------------------------------------------------------
#define SZ_H16  ((size_t)M_TOT * HIDDEN * 2)
#define SZ_CD16 ((size_t)M_TOT * C_DIM * 2)
#define SZ_CD32 ((size_t)M_TOT * C_DIM * 4)
#define OFF_XA  (SZ_H16)
#define OFF_T   (OFF_XA + SZ_CD16)
#define OFF_X1F (OFF_T + SZ_CD32)
#define OFF_X1H (OFF_X1F + SZ_CD32)
#define POOLSZ  (OFF_X1H + SZ_CD16)

__device__ __align__(256) char g_pool[POOLSZ];

__device__ __half g_wq[QKV_N * C_DIM];
__device__ __half g_wp[C_DIM * C_DIM];
__device__ __half g_w1[HIDDEN * C_DIM];
__device__ __half g_w2[C_DIM * HIDDEN];
__device__ float  g_rpbd[NH * 64 * 64];

// ---------------------------------------------------------------------------
__device__ __forceinline__ int map_row(int m) {
    int w    = m >> 6;
    int t    = m & 63;
    int b    = w >> 10;
    int widx = w & 1023;
    int wh   = widx >> 5;
    int ww   = widx & 31;
    int r    = t >> 3;
    int c    = t & 7;
    int h    = (wh * 8 + r + 4) & 255;
    int wc   = (ww * 8 + c + 4) & 255;
    return (b << 16) | (h << 8) | wc;
}

__device__ __forceinline__ uint32_t smem_to_u32(const void* p) {
    uint32_t a;
    asm("{ .reg .u64 t; cvta.to.shared.u64 t, %1; cvt.u32.u64 %0, t; }" : "=r"(a) : "l"(p));
    return a;
}

#define CP_ASYNC16(dst, src) \
    asm volatile("cp.async.cg.shared.global [%0], [%1], 16;" :: "r"(dst), "l"(src))
#define CP_COMMIT() asm volatile("cp.async.commit_group;")
#define CP_WAIT(n)  asm volatile("cp.async.wait_group %0;" :: "n"(n))

#define LDM_X4(r0, r1, r2, r3, addr) \
    asm volatile("ldmatrix.sync.aligned.m8n8.x4.shared.b16 {%0,%1,%2,%3}, [%4];" \
                 : "=r"(r0), "=r"(r1), "=r"(r2), "=r"(r3) : "r"(addr))
#define LDM_X4_T(r0, r1, r2, r3, addr) \
    asm volatile("ldmatrix.sync.aligned.m8n8.x4.trans.shared.b16 {%0,%1,%2,%3}, [%4];" \
                 : "=r"(r0), "=r"(r1), "=r"(r2), "=r"(r3) : "r"(addr))

#define MMA_F16(d, a, b) \
    asm volatile("mma.sync.aligned.m16n8k16.row.col.f32.f16.f16.f32 " \
                 "{%0,%1,%2,%3}, {%4,%5,%6,%7}, {%8,%9}, {%0,%1,%2,%3};" \
                 : "+f"((d)[0]), "+f"((d)[1]), "+f"((d)[2]), "+f"((d)[3]) \
                 : "r"((a)[0]), "r"((a)[1]), "r"((a)[2]), "r"((a)[3]), \
                   "r"((b)[0]), "r"((b)[1]))

__device__ __forceinline__ uint32_t pk_h2(float x, float y) {
    __half2 t = __floats2half2_rn(x, y);
    return *(uint32_t*)&t;
}

// ---------------------------------------------------------------------------
// Prep kernels
// ---------------------------------------------------------------------------
__global__ __launch_bounds__(256) void prep_x(
    const float* __restrict__ x, uint32_t* __restrict__ xo)
{
    int idx = blockIdx.x * 256 + threadIdx.x;      // M_TOT * 48
    int m = idx / 48, c4 = idx % 48;
    float4 v = *(const float4*)(x + (size_t)map_row(m) * C_DIM + c4 * 4);
    *(uint2*)(xo + ((size_t)m * C_DIM + c4 * 4) / 2) =
        make_uint2(pk_h2(v.x, v.y), pk_h2(v.z, v.w));
}

__global__ __launch_bounds__(256) void prep_w(
    const float* __restrict__ w, uint32_t* __restrict__ wo, int K)
{
    int idx = blockIdx.x * 256 + threadIdx.x;      // rows * K/4
    int k4 = K / 4;
    int row = idx / k4, c4 = idx % k4;
    float4 v = *(const float4*)(w + (size_t)row * K + c4 * 4);
    *(uint2*)(wo + ((size_t)row * K + c4 * 4) / 2) =
        make_uint2(pk_h2(v.x, v.y), pk_h2(v.z, v.w));
}

__global__ void prep_rpb(const float* __restrict__ rpb_table, const int* __restrict__ rel_idx,
                         float* __restrict__ rpbd)
{
    int idx = blockIdx.x * 256 + threadIdx.x;      // NH*4096
    int h = idx >> 12, tj = idx & 4095;
    rpbd[idx] = rpb_table[rel_idx[tj] * NH + h];
}

// ---------------------------------------------------------------------------
// fp16 HMMA GEMM. BM=256, BN=64, BK=64, 256 threads, warps 4(M) x 2(N),
// warp tile 64x32 (16 MMA per 6 ldmatrix). 2-stage cp.async pipeline.
// ---------------------------------------------------------------------------
#define BM   256
#define BK   64
#define RS   144
#define ATB  (256 * RS)       // 36864
#define BTB  (64 * RS)        // 9216
#define SSTG (ATB + BTB)      // 46080
#define MMSMEM (2 * SSTG)     // 92160

template<bool SCATTER, bool DOGELU>
__global__ __launch_bounds__(256, 2) void mm_f16(
    const __half* __restrict__ A, const __half* __restrict__ W,
    const float* __restrict__ bias, uint32_t* __restrict__ Ou,
    float* __restrict__ Of, int N, int K)
{
    extern __shared__ char sm[];
    const uint32_t sbase = smem_to_u32(sm);

    const int tid = threadIdx.x, wid = tid >> 5, lane = tid & 31;
    const int warpM = wid & 3, warpN = wid >> 2;
    const int rowBase = blockIdx.y * BM;
    const int colBase = blockIdx.x * 64;
    const int nch = K / BK;

    // staging bases: thread covers rows (tid>>3)+32t, chunk (tid&7)
    const __half* aSrc0 = A + (size_t)(rowBase + (tid >> 3)) * K + (tid & 7) * 8;
    const __half* bSrc0 = W + (size_t)(colBase + (tid >> 3)) * K + (tid & 7) * 8;
    const uint32_t dDst0 = (tid >> 3) * RS + (tid & 7) * 16;
    const size_t aStep = (size_t)32 * K;

    auto issue = [&](int s, int it) {
        uint32_t sb = sbase + s * SSTG;
        int k0 = it * BK;
        #pragma unroll
        for (int t = 0; t < 8; t++)
            CP_ASYNC16(sb + dDst0 + t * (32 * RS), aSrc0 + k0 + t * aStep);
        #pragma unroll
        for (int t = 0; t < 2; t++)
            CP_ASYNC16(sb + ATB + dDst0 + t * (32 * RS), bSrc0 + k0 + t * aStep);
        CP_COMMIT();
    };

    const uint32_t aRowL = (uint32_t)(warpM * 64 + (lane & 15));
    const uint32_t aColB = (uint32_t)((lane >> 4) * 16);
    const uint32_t bRowL = (uint32_t)(warpN * 32 + (lane & 7) + ((lane >> 4) << 3));
    const uint32_t bColB = (uint32_t)(((lane >> 3) & 1) * 16);

    float acc[4][4][4] = {};

    issue(0, 0);

    for (int it = 0; it < nch; it++) {
        CP_WAIT(0);
        __syncthreads();
        if (it + 1 < nch) issue((it + 1) & 1, it + 1);

        const uint32_t stg = sbase + (it & 1) * SSTG;
        #pragma unroll
        for (int kk = 0; kk < BK; kk += 16) {
            uint32_t ah[4][4], bb[2][4];
            #pragma unroll
            for (int mt = 0; mt < 4; mt++) {
                uint32_t off = (aRowL + mt * 16) * RS + aColB + kk * 2;
                LDM_X4(ah[mt][0], ah[mt][1], ah[mt][2], ah[mt][3], stg + off);
            }
            #pragma unroll
            for (int nt2 = 0; nt2 < 2; nt2++) {
                uint32_t off = ATB + (bRowL + nt2 * 16) * RS + bColB + kk * 2;
                LDM_X4(bb[nt2][0], bb[nt2][1], bb[nt2][2], bb[nt2][3], stg + off);
            }
            #pragma unroll
            for (int mt = 0; mt < 4; mt++) {
                #pragma unroll
                for (int n = 0; n < 4; n++) {
                    uint32_t bf[2] = { bb[n >> 1][(n & 1) * 2], bb[n >> 1][(n & 1) * 2 + 1] };
                    MMA_F16(acc[mt][n], ah[mt], bf);
                }
            }
        }
    }

    // ---- epilogue ----
    const int qid = lane >> 2;
    const int cid2 = (lane & 3) * 2;
    #pragma unroll
    for (int mt = 0; mt < 4; mt++) {
        #pragma unroll
        for (int hf = 0; hf < 2; hf++) {
            int row = rowBase + warpM * 64 + mt * 16 + qid + hf * 8;
            if (SCATTER) row = map_row(row);
            #pragma unroll
            for (int n = 0; n < 4; n++) {
                int col = colBase + warpN * 32 + n * 8 + cid2;
                float2 bv = *(const float2*)(bias + col);
                float ox = acc[mt][n][hf * 2 + 0] + bv.x;
                float oy = acc[mt][n][hf * 2 + 1] + bv.y;
                if (DOGELU) {
                    ox = 0.5f * ox * (1.0f + erff(ox * 0.70710678118654752f));
                    oy = 0.5f * oy * (1.0f + erff(oy * 0.70710678118654752f));
                }
                if (Ou) *(uint32_t*)(Ou + ((size_t)row * N + col) / 2) = pk_h2(ox, oy);
                else    *(float2*)(Of + (size_t)row * N + col) = make_float2(ox, oy);
            }
        }
    }
}

// ---------------------------------------------------------------------------
// Tensor-core attention (unchanged from R11).
// ---------------------------------------------------------------------------
#define AT_SMEM 61440

__global__ __launch_bounds__(256, 2) void attn_mma(
    const __half* __restrict__ qkv, const float* __restrict__ rpbd,
    const float* __restrict__ mask, uint32_t* __restrict__ outp)
{
    extern __shared__ char smraw[];
    const uint32_t sbase = smem_to_u32(smraw);
    const int tid = threadIdx.x, wid = tid >> 5, lane = tid & 31;
    const int u = wid >> 1, mhalf = wid & 1;
    const int wh = blockIdx.x * 4 + u;
    const int w = wh / NH;
    const int hh = wh - w * NH;
    const size_t rowbase = (size_t)w * 64;

    const uint32_t Qs = sbase + u * 15360;
    const uint32_t Ks = Qs + 5120;
    const uint32_t Vs = Qs + 10240;

    {
        int t64 = mhalf * 32 + lane;
        int r0  = t64 >> 2;
        int seg = t64 & 3;
        const __half* base = qkv + rowbase * QKV_N + hh * 32 + seg * 8;
        #pragma unroll
        for (int it = 0; it < 4; it++) {
            int row = it * 16 + r0;
            const __half* src = base + (size_t)row * QKV_N;
            uint32_t d = row * 80 + seg * 16;
            CP_ASYNC16(Qs + d, src);
            CP_ASYNC16(Ks + d, src + 192);
            CP_ASYNC16(Vs + d, src + 384);
        }
        CP_COMMIT();
    }
    CP_WAIT(0);
    __syncthreads();

    const int qid = lane >> 2, cid = lane & 3;
    const int mbase = mhalf * 32;

    const uint32_t aRow  = (uint32_t)(mbase + (lane & 15));
    const uint32_t aColB = (uint32_t)((lane >> 4) * 16);
    const uint32_t bRow  = (uint32_t)((lane & 7) + ((lane >> 4) << 3));
    const uint32_t bColB = (uint32_t)(((lane >> 3) & 1) * 16);

    float s[2][8][4] = {};
    #pragma unroll
    for (int ks = 0; ks < 2; ks++) {
        uint32_t qf[2][4];
        #pragma unroll
        for (int mt = 0; mt < 2; mt++)
            LDM_X4(qf[mt][0], qf[mt][1], qf[mt][2], qf[mt][3],
                   Qs + (aRow + mt * 16) * 80 + aColB + ks * 32);
        #pragma unroll
        for (int p = 0; p < 4; p++) {
            uint32_t kb[4];
            LDM_X4(kb[0], kb[1], kb[2], kb[3],
                   Ks + (bRow + p * 16) * 80 + bColB + ks * 32);
            #pragma unroll
            for (int mt = 0; mt < 2; mt++) {
                #pragma unroll
                for (int nn = 0; nn < 2; nn++) {
                    uint32_t bf[2] = { kb[nn * 2], kb[nn * 2 + 1] };
                    MMA_F16(s[mt][p * 2 + nn], qf[mt], bf);
                }
            }
        }
    }

    const float* mrow = mask + (size_t)(w & 1023) * 4096;
    const float* rrow = rpbd + hh * 4096;
    uint32_t pf[2][4][4];
    float inva[2], invb[2];
    #pragma unroll
    for (int mt = 0; mt < 2; mt++) {
        int t0 = mbase + mt * 16 + qid;
        int t1 = t0 + 8;
        float mx0 = -1e30f, mx1 = -1e30f;
        #pragma unroll
        for (int n = 0; n < 8; n++) {
            int j = n * 8 + cid * 2;
            float2 r0 = *(const float2*)(rrow + t0 * 64 + j);
            float2 r1 = *(const float2*)(rrow + t1 * 64 + j);
            float2 m0 = *(const float2*)(mrow + t0 * 64 + j);
            float2 m1 = *(const float2*)(mrow + t1 * 64 + j);
            s[mt][n][0] = fmaf(s[mt][n][0], SCALE_F, r0.x + m0.x);
            s[mt][n][1] = fmaf(s[mt][n][1], SCALE_F, r0.y + m0.y);
            s[mt][n][2] = fmaf(s[mt][n][2], SCALE_F, r1.x + m1.x);
            s[mt][n][3] = fmaf(s[mt][n][3], SCALE_F, r1.y + m1.y);
            mx0 = fmaxf(mx0, fmaxf(s[mt][n][0], s[mt][n][1]));
            mx1 = fmaxf(mx1, fmaxf(s[mt][n][2], s[mt][n][3]));
        }
        mx0 = fmaxf(mx0, __shfl_xor_sync(0xffffffffu, mx0, 1));
        mx0 = fmaxf(mx0, __shfl_xor_sync(0xffffffffu, mx0, 2));
        mx1 = fmaxf(mx1, __shfl_xor_sync(0xffffffffu, mx1, 1));
        mx1 = fmaxf(mx1, __shfl_xor_sync(0xffffffffu, mx1, 2));

        float sm0 = 0.f, sm1 = 0.f;
        #pragma unroll
        for (int n = 0; n < 8; n++) {
            s[mt][n][0] = expf(s[mt][n][0] - mx0);
            s[mt][n][1] = expf(s[mt][n][1] - mx0);
            s[mt][n][2] = expf(s[mt][n][2] - mx1);
            s[mt][n][3] = expf(s[mt][n][3] - mx1);
            sm0 += s[mt][n][0] + s[mt][n][1];
            sm1 += s[mt][n][2] + s[mt][n][3];
        }
        sm0 += __shfl_xor_sync(0xffffffffu, sm0, 1);
        sm0 += __shfl_xor_sync(0xffffffffu, sm0, 2);
        sm1 += __shfl_xor_sync(0xffffffffu, sm1, 1);
        sm1 += __shfl_xor_sync(0xffffffffu, sm1, 2);
        inva[mt] = 1.f / sm0;
        invb[mt] = 1.f / sm1;

        #pragma unroll
        for (int k2 = 0; k2 < 4; k2++) {
            pf[mt][k2][0] = pk_h2(s[mt][2 * k2][0],     s[mt][2 * k2][1]);
            pf[mt][k2][1] = pk_h2(s[mt][2 * k2][2],     s[mt][2 * k2][3]);
            pf[mt][k2][2] = pk_h2(s[mt][2 * k2 + 1][0], s[mt][2 * k2 + 1][1]);
            pf[mt][k2][3] = pk_h2(s[mt][2 * k2 + 1][2], s[mt][2 * k2 + 1][3]);
        }
    }

    float o[2][4][4] = {};
    const uint32_t vRow  = (uint32_t)(lane & 15);
    const uint32_t vColB = (uint32_t)((lane >> 4) * 16);
    #pragma unroll
    for (int k2 = 0; k2 < 4; k2++) {
        #pragma unroll
        for (int p = 0; p < 2; p++) {
            uint32_t vb[4];
            LDM_X4_T(vb[0], vb[1], vb[2], vb[3],
                     Vs + (k2 * 16 + vRow) * 80 + vColB + p * 32);
            #pragma unroll
            for (int mt = 0; mt < 2; mt++) {
                #pragma unroll
                for (int nn = 0; nn < 2; nn++) {
                    uint32_t bf[2] = { vb[nn * 2], vb[nn * 2 + 1] };
                    MMA_F16(o[mt][p * 2 + nn], pf[mt][k2], bf);
                }
            }
        }
    }

    #pragma unroll
    for (int mt = 0; mt < 2; mt++) {
        int t0 = mbase + mt * 16 + qid;
        int t1 = t0 + 8;
        uint32_t* o0 = outp + ((rowbase + t0) * C_DIM + hh * 32) / 2;
        uint32_t* o1 = outp + ((rowbase + t1) * C_DIM + hh * 32) / 2;
        #pragma unroll
        for (int nt = 0; nt < 4; nt++) {
            int c2 = (nt * 8 + cid * 2) >> 1;
            o0[c2] = pk_h2(o[mt][nt][0] * inva[mt], o[mt][nt][1] * inva[mt]);
            o1[c2] = pk_h2(o[mt][nt][2] * invb[mt], o[mt][nt][3] * invb[mt]);
        }
    }
}

// ---------------------------------------------------------------------------
// LN kernels (unchanged)
// ---------------------------------------------------------------------------
__global__ __launch_bounds__(256) void ln1_k(
    const float* __restrict__ y, const float* __restrict__ resx,
    const float* __restrict__ g, const float* __restrict__ b,
    float* __restrict__ of, uint32_t* __restrict__ oh)
{
    const size_t token = (size_t)blockIdx.x * 8 + (threadIdx.x >> 5);
    const int lane = threadIdx.x & 31;
    const size_t yb = token * C_DIM;

    float v[6];
    float sum = 0.f;
    #pragma unroll
    for (int i = 0; i < 6; i++) { v[i] = y[yb + lane + 32 * i]; sum += v[i]; }
    #pragma unroll
    for (int o = 16; o; o >>= 1) sum += __shfl_xor_sync(0xffffffffu, sum, o);
    const float mu = sum * (1.f / 192.f);
    float sq = 0.f;
    #pragma unroll
    for (int i = 0; i < 6; i++) { float d = v[i] - mu; sq = fmaf(d, d, sq); }
    #pragma unroll
    for (int o = 16; o; o >>= 1) sq += __shfl_xor_sync(0xffffffffu, sq, o);
    const float inv = rsqrtf(sq * (1.f / 192.f) + 1e-5f);

    #pragma unroll
    for (int i = 0; i < 6; i++) {
        int c = lane + 32 * i;
        float r = resx[yb + c] + (v[i] - mu) * inv * g[c] + b[c];
        of[yb + c] = r;
        ((__half*)oh)[yb + c] = __float2half_rn(r);
    }
}

__global__ __launch_bounds__(256) void ln2_k(
    const float* __restrict__ y, const float* __restrict__ r,
    const float* __restrict__ g, const float* __restrict__ b,
    float* __restrict__ outp)
{
    const size_t token = (size_t)blockIdx.x * 8 + (threadIdx.x >> 5);
    const int lane = threadIdx.x & 31;
    const size_t yb = token * C_DIM;

    float v[6];
    float sum = 0.f;
    #pragma unroll
    for (int i = 0; i < 6; i++) { v[i] = y[yb + lane + 32 * i]; sum += v[i]; }
    #pragma unroll
    for (int o = 16; o; o >>= 1) sum += __shfl_xor_sync(0xffffffffu, sum, o);
    const float mu = sum * (1.f / 192.f);
    float sq = 0.f;
    #pragma unroll
    for (int i = 0; i < 6; i++) { float d = v[i] - mu; sq = fmaf(d, d, sq); }
    #pragma unroll
    for (int o = 16; o; o >>= 1) sq += __shfl_xor_sync(0xffffffffu, sq, o);
    const float inv = rsqrtf(sq * (1.f / 192.f) + 1e-5f);

    #pragma unroll
    for (int i = 0; i < 6; i++) {
        int c = lane + 32 * i;
        outp[yb + c] = r[yb + c] + (v[i] - mu) * inv * g[c] + b[c];
    }
}

// ---------------------------------------------------------------------------
// Launch (qkv GEMM at capture slot 4)
// ---------------------------------------------------------------------------
extern "C" void kernel_launch(void* const* d_in, const int* in_sizes, int n_in,
                              void* d_out, int out_size)
{
    const float* x      = (const float*)d_in[0];
    const float* mask   = (const float*)d_in[1];
    const int*   relidx = (const int*)  d_in[2];
    const float* qkv_w  = (const float*)d_in[3];
    const float* qkv_b  = (const float*)d_in[4];
    const float* proj_w = (const float*)d_in[5];
    const float* proj_b = (const float*)d_in[6];
    const float* rpb    = (const float*)d_in[7];
    const float* n1g    = (const float*)d_in[8];
    const float* n1b    = (const float*)d_in[9];
    const float* n2g    = (const float*)d_in[10];
    const float* n2b    = (const float*)d_in[11];
    const float* fc1w   = (const float*)d_in[12];
    const float* fc1b   = (const float*)d_in[13];
    const float* fc2w   = (const float*)d_in[14];
    const float* fc2b   = (const float*)d_in[15];
    float* out = (float*)d_out;

    char* pool;
    cudaGetSymbolAddress((void**)&pool, g_pool);
    __half*   q   = (__half*)(pool);
    __half*   h   = (__half*)(pool);
    __half*   xb  = (__half*)(pool + OFF_XA);
    __half*   a   = (__half*)(pool + OFF_XA);
    float*    tb  = (float*)(pool + OFF_T);
    float*    x1f = (float*)(pool + OFF_X1F);
    uint32_t* x1h = (uint32_t*)(pool + OFF_X1H);

    __half *wq, *wp, *w1, *w2;
    float* rpbd;
    cudaGetSymbolAddress((void**)&wq, g_wq);
    cudaGetSymbolAddress((void**)&wp, g_wp);
    cudaGetSymbolAddress((void**)&w1, g_w1);
    cudaGetSymbolAddress((void**)&w2, g_w2);
    cudaGetSymbolAddress((void**)&rpbd, g_rpbd);

    cudaFuncSetAttribute(mm_f16<false, false>, cudaFuncAttributeMaxDynamicSharedMemorySize, MMSMEM);
    cudaFuncSetAttribute(mm_f16<true,  false>, cudaFuncAttributeMaxDynamicSharedMemorySize, MMSMEM);
    cudaFuncSetAttribute(mm_f16<false, true >, cudaFuncAttributeMaxDynamicSharedMemorySize, MMSMEM);
    cudaFuncSetAttribute(attn_mma, cudaFuncAttributeMaxDynamicSharedMemorySize, AT_SMEM);

    // 1. x -> window-ordered fp16
    prep_x<<<(M_TOT * 48) / 256, 256>>>(x, (uint32_t*)xb);
    // 2. dense rpb
    prep_rpb<<<(NH * 4096) / 256, 256>>>(rpb, relidx, rpbd);
    // 3. qkv weights
    prep_w<<<(QKV_N * (C_DIM / 4)) / 256, 256>>>(qkv_w, (uint32_t*)wq, C_DIM);
    // 4. qkv GEMM  (capture slot)
    mm_f16<false, false><<<dim3(QKV_N / 64, M_TOT / BM), 256, MMSMEM>>>(
        xb, wq, qkv_b, (uint32_t*)q, nullptr, QKV_N, C_DIM);
    // 5. attention (tensor cores)
    attn_mma<<<NWIN * NH / 4, 256, AT_SMEM>>>(q, rpbd, mask, (uint32_t*)a);
    // 6. proj weights
    prep_w<<<(C_DIM * (C_DIM / 4)) / 256, 256>>>(proj_w, (uint32_t*)wp, C_DIM);
    // 7. proj GEMM + scatter, fp32 out
    mm_f16<true, false><<<dim3(C_DIM / 64, M_TOT / BM), 256, MMSMEM>>>(
        a, wp, proj_b, nullptr, tb, C_DIM, C_DIM);
    // 8. LN1
    ln1_k<<<M_TOT / 8, 256>>>(tb, x, n1g, n1b, x1f, x1h);
    // 9. fc1 weights
    prep_w<<<(HIDDEN * (C_DIM / 4)) / 256, 256>>>(fc1w, (uint32_t*)w1, C_DIM);
    // 10. fc1 + GELU
    mm_f16<false, true><<<dim3(HIDDEN / 64, M_TOT / BM), 256, MMSMEM>>>(
        (const __half*)x1h, w1, fc1b, (uint32_t*)h, nullptr, HIDDEN, C_DIM);
    // 11. fc2 weights
    prep_w<<<(C_DIM * (HIDDEN / 4)) / 256, 256>>>(fc2w, (uint32_t*)w2, HIDDEN);
    // 12. fc2
    mm_f16<false, false><<<dim3(C_DIM / 64, M_TOT / BM), 256, MMSMEM>>>(
        h, w2, fc2b, nullptr, tb, C_DIM, HIDDEN);
    // 13. LN2 -> out
    ln2_k<<<M_TOT / 8, 256>>>(tb, x1f, n2g, n2b, out);
}